// round 1
// baseline (speedup 1.0000x reference)
#include <cuda_runtime.h>
#include <math.h>

#define BB 8
#define VV 2048
#define DD 16
#define FF 64
#define EMBD 32
#define FEAT 16
#define HID 32
#define BV (BB*VV)            // 16384
#define BVD (BV*DD)           // 262144
#define BVDF (BVD*FF)         // 16777216
#define VD (VV*DD)            // 32768
#define BIGC 1e9f

// ---------------- scratch (device globals; no allocations allowed) ----------
__device__ float g_embc[VV*EMBD];
__device__ float g_enc[BV*FF];
__device__ float g_initial[BVDF];
__device__ float g_state[BVDF];
__device__ float g_h[BVDF];          // h, later reused as msg
__device__ float g_agg[BV*FF];
__device__ float g_nw[BVD];
__device__ float g_attnin[BVD];
__device__ float g_norm[BVD];
__device__ float g_ns[BV*FF];
__device__ float g_dualvars[BV];
__device__ float g_fc[BB];
__device__ float g_dq[BVD/256];      // 1024 partials
__device__ float g_dd[BV/256];       // 64 partials

// ---------------- 1. emb row-normalize --------------------------------------
__global__ void k_emb(const float* __restrict__ emb){
    int warp = (blockIdx.x*blockDim.x + threadIdx.x) >> 5;
    int lane = threadIdx.x & 31;
    if (warp >= VV) return;
    float x = emb[warp*EMBD + lane];          // EMB==32 == warp size
    float s = x*x;
    #pragma unroll
    for (int o=16;o;o>>=1) s += __shfl_xor_sync(0xffffffffu, s, o);
    float nrm = sqrtf(s);
    float scale = fminf(1.0f, 1.0f / fmaxf(nrm, 1e-12f));
    g_embc[warp*EMBD + lane] = x*scale;
}

// ---------------- 2. encoder: concat(emb_c, feat) @ enc_W + b ---------------
__global__ void k_enc(const float* __restrict__ nf, const float* __restrict__ W,
                      const float* __restrict__ bvec){
    int node = blockIdx.x*4 + (threadIdx.x >> 6);
    int f = threadIdx.x & 63;
    int v = node & (VV-1);
    float acc = bvec[f];
    const float* ev = g_embc + v*EMBD;
    const float* nr = nf + node*FEAT;
    #pragma unroll
    for (int k=0;k<EMBD;k++) acc += ev[k]*W[k*FF+f];
    #pragma unroll
    for (int k=0;k<FEAT;k++) acc += nr[k]*W[(EMBD+k)*FF+f];
    g_enc[node*FF+f] = acc;
}

// ---------------- 3. initial = gather(enc, adj)*(1-mask); state=initial -----
__global__ void k_gather_init(const int* __restrict__ adj, const int* __restrict__ num_nodes){
    int t = blockIdx.x*256 + threadIdx.x;          // over BVD*16 float4 chunks
    int f4 = t & 15; int row = t >> 4;
    int node = row >> 4; int b = node >> 11;
    int a = adj[row];
    float m = (a == num_nodes[b]) ? 0.f : 1.f;
    float4 v = ((const float4*)(g_enc + ((b<<11)+a)*FF))[f4];
    v.x*=m; v.y*=m; v.z*=m; v.w*=m;
    ((float4*)(g_initial + row*FF))[f4] = v;
    ((float4*)(g_state   + row*FF))[f4] = v;
}

// ---------------- 4. h = tanh(state @ gat_W + gat_b) ------------------------
__global__ void k_gat(const float* __restrict__ W, const float* __restrict__ bvec){
    __shared__ float Ws[64*64];
    __shared__ float Rs[16*65];
    int t = threadIdx.x;
    for (int i=t;i<4096;i+=256) Ws[i] = W[i];
    int rbase = blockIdx.x*16;
    for (int i=t;i<1024;i+=256){ int r=i>>6, k=i&63; Rs[r*65+k] = g_state[rbase*FF + i]; }
    __syncthreads();
    int c = t & 63; int r0 = t >> 6;               // 4 row groups
    float acc[4];
    float bc = bvec[c];
    #pragma unroll
    for (int i=0;i<4;i++) acc[i] = bc;
    for (int k=0;k<64;k++){
        float w = Ws[k*64+c];
        #pragma unroll
        for (int i=0;i<4;i++) acc[i] += Rs[(r0+4*i)*65+k]*w;
    }
    #pragma unroll
    for (int i=0;i<4;i++) g_h[(rbase + r0 + 4*i)*FF + c] = tanhf(acc[i]);
}

// ---------------- 5. scores -> softmax(D) -> agg -----------------------------
__global__ void k_attn(const float* __restrict__ gat_a, const int* __restrict__ adj,
                       const int* __restrict__ num_nodes){
    __shared__ float sa[FF];
    if (threadIdx.x < FF) sa[threadIdx.x] = gat_a[threadIdx.x];
    __syncthreads();
    int lane = threadIdx.x & 31;
    int node = blockIdx.x*8 + (threadIdx.x >> 5);
    int b = node >> 11;
    const float* hb = g_h + (size_t)node*DD*FF;
    float sc = -1e30f;
    if (lane < DD){
        float s = 0.f;
        #pragma unroll 8
        for (int k=0;k<FF;k++) s += hb[lane*FF+k]*sa[k];
        int a = adj[node*DD+lane];
        sc = s - ((a==num_nodes[b]) ? BIGC : 0.f);
    }
    float mx = sc;
    #pragma unroll
    for (int o=16;o;o>>=1) mx = fmaxf(mx, __shfl_xor_sync(0xffffffffu, mx, o));
    float e = (lane < DD) ? expf(sc - mx) : 0.f;
    float sm = e;
    #pragma unroll
    for (int o=16;o;o>>=1) sm += __shfl_xor_sync(0xffffffffu, sm, o);
    float attn = e / sm;
    float a0=0.f, a1=0.f;
    #pragma unroll
    for (int d=0;d<DD;d++){
        float ad = __shfl_sync(0xffffffffu, attn, d);
        a0 += ad * hb[d*FF + lane];
        a1 += ad * hb[d*FF + lane + 32];
    }
    g_agg[node*FF + lane]      = a0;
    g_agg[node*FF + lane + 32] = a1;
}

// ---------------- 6. msg = gather(agg)*(1-mask) + initial  (into g_h) -------
__global__ void k_msg(const int* __restrict__ adj, const int* __restrict__ num_nodes){
    int t = blockIdx.x*256 + threadIdx.x;
    int f4 = t & 15; int row = t >> 4;
    int node = row >> 4; int b = node >> 11;
    int a = adj[row];
    float m = (a == num_nodes[b]) ? 0.f : 1.f;
    float4 g = ((const float4*)(g_agg + ((b<<11)+a)*FF))[f4];
    float4 ini = ((const float4*)(g_initial + row*FF))[f4];
    float4 o;
    o.x = g.x*m + ini.x; o.y = g.y*m + ini.y; o.z = g.z*m + ini.z; o.w = g.w*m + ini.w;
    ((float4*)(g_h + row*FF))[f4] = o;
}

// ---------------- 7. fused GRU: state = GRU(msg, state) ---------------------
// blockDim = 192, 64 rows/block. Transposed weights in shared, float4 reads.
#define GRU_WPAD 68
#define GRU_SMEM ((2*192*GRU_WPAD + 64 + 64 + 192 + 192) * (int)sizeof(float))
__global__ void k_gru(const float* __restrict__ Wx, const float* __restrict__ Wh,
                      const float* __restrict__ bvec){
    extern __shared__ float sh[];
    float* WxT  = sh;                          // [192][68]
    float* WhT  = sh + 192*GRU_WPAD;
    float* mrow = sh + 2*192*GRU_WPAD;         // 64
    float* srow = mrow + 64;                   // 64
    float* xs   = srow + 64;                   // 192
    float* hs   = xs + 192;                    // 192
    int t = threadIdx.x;
    for (int i=t;i<64*192;i+=192){
        int k = i/192, j = i - k*192;
        WxT[j*GRU_WPAD + k] = Wx[i];
        WhT[j*GRU_WPAD + k] = Wh[i];
    }
    float bj = bvec[t];
    int base = blockIdx.x*64;
    __syncthreads();
    for (int r=0;r<64;r++){
        int row = base + r;
        if (t < 64)       mrow[t]    = g_h[row*FF + t];
        else if (t < 128) srow[t-64] = g_state[row*FF + (t-64)];
        __syncthreads();                       // stage done; prev gates done
        float xv = bj, hv = 0.f;
        const float4* wx4 = (const float4*)(WxT + t*GRU_WPAD);
        const float4* wh4 = (const float4*)(WhT + t*GRU_WPAD);
        const float4* m4  = (const float4*)mrow;
        const float4* s4  = (const float4*)srow;
        #pragma unroll
        for (int kk=0;kk<16;kk++){
            float4 wx = wx4[kk], wh = wh4[kk];
            float4 mv = m4[kk],  sv = s4[kk];
            xv += wx.x*mv.x + wx.y*mv.y + wx.z*mv.z + wx.w*mv.w;
            hv += wh.x*sv.x + wh.y*sv.y + wh.z*sv.z + wh.w*sv.w;
        }
        xs[t] = xv; hs[t] = hv;
        __syncthreads();                       // x,hm ready
        if (t < 64){
            float sold = g_state[row*FF + t];  // global read: still old value
            float z  = 1.f/(1.f + expf(-(xs[t]      + hs[t])));
            float rr = 1.f/(1.f + expf(-(xs[t+64]   + hs[t+64])));
            float cand = tanhf(xs[t+128] + rr*hs[t+128]);
            g_state[row*FF + t] = z*sold + (1.f - z)*cand;
        }
        // no third sync: next stage only writes mrow/srow (gates don't read them)
    }
}

// ---------------- 8. generic 64->32->1 MLP head ------------------------------
// mode 0: g_state(BVD rows) -> g_nw  with dec weights
// mode 1: g_ns  (BV rows)   -> g_dualvars with dual weights
__global__ void k_mlp(int mode, const float* __restrict__ W1, const float* __restrict__ b1,
                      const float* __restrict__ W2, const float* __restrict__ b2){
    __shared__ float S[128*65];
    __shared__ float W1s[64*32];
    __shared__ float b1s[32], W2s[32];
    const float* in = mode ? g_ns : g_state;
    float* out      = mode ? g_dualvars : g_nw;
    int t = threadIdx.x;
    int base = blockIdx.x*128;
    for (int i=t;i<2048;i+=128) W1s[i] = W1[i];
    if (t < 32){ b1s[t] = b1[t]; W2s[t] = W2[t]; }
    for (int c=0;c<64;c++){
        int lin = c*128 + t;
        int r = lin >> 6, k = lin & 63;
        S[r*65 + k] = in[(size_t)base*FF + lin];
    }
    __syncthreads();
    float acc[32];
    #pragma unroll
    for (int h=0;h<32;h++) acc[h] = b1s[h];
    const float* myrow = S + t*65;
    for (int k=0;k<64;k++){
        float s = myrow[k];
        #pragma unroll
        for (int h=0;h<32;h++) acc[h] += s*W1s[k*32+h];
    }
    float o = b2[0];
    #pragma unroll
    for (int h=0;h<32;h++) o += tanhf(acc[h])*W2s[h];
    out[base + t] = o;
}

// ---------------- 9. incoming-gather softmax ---------------------------------
__global__ void k_inattn(const int* __restrict__ in_idx, const int* __restrict__ inv_adj,
                         const int* __restrict__ num_nodes){
    int lane = threadIdx.x & 31;
    int node = blockIdx.x*8 + (threadIdx.x >> 5);
    int b = node >> 11;
    float sc = -1e30f;
    if (lane < DD){
        int idx = in_idx[node*DD + lane];
        float inc = g_nw[b*VD + idx];
        int ia = inv_adj[node*DD + lane];
        sc = inc - ((ia == num_nodes[b]) ? BIGC : 0.f);
    }
    float mx = sc;
    #pragma unroll
    for (int o=16;o;o>>=1) mx = fmaxf(mx, __shfl_xor_sync(0xffffffffu, mx, o));
    float e = (lane < DD) ? expf(sc - mx) : 0.f;
    float sm = e;
    #pragma unroll
    for (int o=16;o;o>>=1) sm += __shfl_xor_sync(0xffffffffu, sm, o);
    if (lane < DD) g_attnin[node*DD + lane] = e / sm;
}

// ---------------- 10. rev-gather + masked softmax -> normalized --------------
__global__ void k_revnorm(const int* __restrict__ rev_idx, const int* __restrict__ adj,
                          const int* __restrict__ num_nodes){
    int lane = threadIdx.x & 31;
    int node = blockIdx.x*8 + (threadIdx.x >> 5);
    int b = node >> 11;
    float sc = -1e30f;
    if (lane < DD){
        int ridx = rev_idx[node*DD + lane];
        float val = g_attnin[b*VD + ridx];
        int a = adj[node*DD + lane];
        sc = val - ((a == num_nodes[b]) ? BIGC : 0.f);
    }
    float mx = sc;
    #pragma unroll
    for (int o=16;o;o>>=1) mx = fmaxf(mx, __shfl_xor_sync(0xffffffffu, mx, o));
    float e = (lane < DD) ? expf(sc - mx) : 0.f;
    float sm = e;
    #pragma unroll
    for (int o=16;o;o>>=1) sm += __shfl_xor_sync(0xffffffffu, sm, o);
    if (lane < DD) g_norm[node*DD + lane] = e / sm;
}

// ---------------- 11. flow fixed-point, one block per batch ------------------
#define FLOW_SMEM ((VD + 2*VV) * (int)sizeof(float))
__global__ void k_flow(const float* __restrict__ demands, const int* __restrict__ inv_adj,
                       const int* __restrict__ in_idx, const int* __restrict__ num_nodes){
    extern __shared__ float sh[];
    float* flow = sh;             // VD
    float* infl = sh + VD;        // VV
    float* sup  = infl + VV;      // VV
    int b = blockIdx.x, t = threadIdx.x;
    int nn = num_nodes[b];
    for (int v=t; v<VV; v+=1024) sup[v] = fmaxf(-demands[b*VV + v], 0.f);
    __syncthreads();
    for (int i=t; i<VD; i+=1024) flow[i] = g_norm[b*VD + i] * sup[i>>4];
    __syncthreads();
    for (int it=0; it<10; it++){
        for (int v=t; v<VV; v+=1024){
            const int* ip = in_idx  + ((size_t)b*VV + v)*DD;
            const int* vp = inv_adj + ((size_t)b*VV + v)*DD;
            float s = 0.f;
            #pragma unroll
            for (int d=0;d<DD;d++){
                float m = (vp[d]==nn) ? 0.f : 1.f;
                s += flow[ip[d]] * m;
            }
            infl[v] = s;
        }
        __syncthreads();
        for (int i=t; i<VD; i+=1024) flow[i] = g_norm[b*VD + i] * (infl[i>>4] + sup[i>>4]);
        __syncthreads();
    }
    float c = 0.f;
    for (int i=t; i<VD; i+=1024) c += flow[i]*flow[i];
    infl[t] = c; __syncthreads();
    for (int s=512; s>0; s>>=1){ if (t < s) infl[t] += infl[t+s]; __syncthreads(); }
    if (t == 0) g_fc[b] = infl[0];
}

// ---------------- 12. node_states = state.sum(d) ------------------------------
__global__ void k_nodestates(){
    int t = blockIdx.x*256 + threadIdx.x;      // over BV*FF
    int f = t & 63; int node = t >> 6;
    float s = 0.f;
    #pragma unroll
    for (int d=0; d<DD; d++) s += g_state[((size_t)node*DD + d)*FF + f];
    g_ns[t] = s;
}

// ---------------- 13. dual iterations + quad cost partials --------------------
__global__ void k_dual(const int* __restrict__ adj, const int* __restrict__ num_nodes){
    __shared__ float red[256];
    int idx = blockIdx.x*256 + threadIdx.x;    // edge row
    int b = idx >> 15; int node = idx >> 4;
    int a = adj[idx]; int nn = num_nodes[b];
    float mask = (a==nn) ? 1.f : 0.f;
    float valid = 1.f - mask;
    float dv  = g_dualvars[node];
    float dtr = g_dualvars[(b<<11) + a] * valid;
    float dd  = dtr - mask*dv;
    float f = 0.f, ac = 0.f;
    #pragma unroll
    for (int i=0;i<10;i++){
        float g = 2.f*f + dd;
        ac = 0.9f*ac + 0.01f*g;
        f = fmaxf(f - ac, 0.f) * valid;
    }
    float c = f*f + dd*f;
    red[threadIdx.x] = c; __syncthreads();
    for (int s=128; s>0; s>>=1){ if (threadIdx.x < s) red[threadIdx.x] += red[threadIdx.x+s]; __syncthreads(); }
    if (threadIdx.x == 0) g_dq[blockIdx.x] = red[0];
}

// ---------------- 14. dual demand partials -----------------------------------
__global__ void k_dualdem(const float* __restrict__ demands){
    __shared__ float red[256];
    int idx = blockIdx.x*256 + threadIdx.x;    // node
    red[threadIdx.x] = g_dualvars[idx] * demands[idx];
    __syncthreads();
    for (int s=128; s>0; s>>=1){ if (threadIdx.x < s) red[threadIdx.x] += red[threadIdx.x+s]; __syncthreads(); }
    if (threadIdx.x == 0) g_dd[blockIdx.x] = red[0];
}

// ---------------- 15. finalize: out[b] = fc - dq + ddm -------------------------
__global__ void k_finalize(float* __restrict__ out){
    int w = threadIdx.x >> 5, lane = threadIdx.x & 31;
    if (w < BB){
        float dq = 0.f;
        #pragma unroll
        for (int i=0;i<4;i++) dq += g_dq[w*128 + lane + 32*i];
        float ddm = (lane < 8) ? g_dd[w*8 + lane] : 0.f;
        #pragma unroll
        for (int o=16;o;o>>=1){
            dq  += __shfl_xor_sync(0xffffffffu, dq,  o);
            ddm += __shfl_xor_sync(0xffffffffu, ddm, o);
        }
        if (lane == 0) out[w] = g_fc[w] - dq + ddm;
    }
}

// ---------------- launcher -----------------------------------------------------
extern "C" void kernel_launch(void* const* d_in, const int* in_sizes, int n_in,
                              void* d_out, int out_size){
    const float* node_features = (const float*)d_in[0];
    const float* demands       = (const float*)d_in[1];
    const float* emb           = (const float*)d_in[2];
    const float* enc_W         = (const float*)d_in[3];
    const float* enc_b         = (const float*)d_in[4];
    const float* gat_W         = (const float*)d_in[5];
    const float* gat_b         = (const float*)d_in[6];
    const float* gat_a         = (const float*)d_in[7];
    const float* gru_Wx        = (const float*)d_in[8];
    const float* gru_Wh        = (const float*)d_in[9];
    const float* gru_b         = (const float*)d_in[10];
    const float* dec_W1        = (const float*)d_in[11];
    const float* dec_b1        = (const float*)d_in[12];
    const float* dec_W2        = (const float*)d_in[13];
    const float* dec_b2        = (const float*)d_in[14];
    const float* dual_W1       = (const float*)d_in[15];
    const float* dual_b1       = (const float*)d_in[16];
    const float* dual_W2       = (const float*)d_in[17];
    const float* dual_b2       = (const float*)d_in[18];
    const int*   adj           = (const int*)d_in[19];
    const int*   inv_adj       = (const int*)d_in[20];
    const int*   in_idx        = (const int*)d_in[21];
    const int*   rev_idx       = (const int*)d_in[22];
    const int*   num_nodes     = (const int*)d_in[23];
    float* out = (float*)d_out;

    cudaFuncSetAttribute(k_gru,  cudaFuncAttributeMaxDynamicSharedMemorySize, GRU_SMEM);
    cudaFuncSetAttribute(k_flow, cudaFuncAttributeMaxDynamicSharedMemorySize, FLOW_SMEM);

    k_emb<<<VV*32/256, 256>>>(emb);
    k_enc<<<BV/4, 256>>>(node_features, enc_W, enc_b);
    k_gather_init<<<BVD*16/256, 256>>>(adj, num_nodes);

    for (int l=0; l<2; l++){
        k_gat <<<BVD/16, 256>>>(gat_W, gat_b);
        k_attn<<<BV/8,   256>>>(gat_a, adj, num_nodes);
        k_msg <<<BVD*16/256, 256>>>(adj, num_nodes);
        k_gru <<<BVD/64, 192, GRU_SMEM>>>(gru_Wx, gru_Wh, gru_b);
    }

    // flow branch
    k_mlp<<<BVD/128, 128>>>(0, dec_W1, dec_b1, dec_W2, dec_b2);
    k_inattn <<<BV/8, 256>>>(in_idx, inv_adj, num_nodes);
    k_revnorm<<<BV/8, 256>>>(rev_idx, adj, num_nodes);
    k_flow<<<BB, 1024, FLOW_SMEM>>>(demands, inv_adj, in_idx, num_nodes);

    // dual branch
    k_nodestates<<<BV*FF/256, 256>>>();
    k_mlp<<<BV/128, 128>>>(1, dual_W1, dual_b1, dual_W2, dual_b2);
    k_dual<<<BVD/256, 256>>>(adj, num_nodes);
    k_dualdem<<<BV/256, 256>>>(demands);

    k_finalize<<<1, 256>>>(out);
}

// round 2
// speedup vs baseline: 2.1729x; 2.1729x over previous
#include <cuda_runtime.h>
#include <math.h>

#define BB 8
#define VV 2048
#define DD 16
#define FF 64
#define EMBD 32
#define FEAT 16
#define HID 32
#define BV (BB*VV)            // 16384
#define BVD (BV*DD)           // 262144
#define BVDF (BVD*FF)         // 16777216
#define VD (VV*DD)            // 32768
#define BIGC 1e9f

// ---------------- scratch (device globals; no allocations allowed) ----------
__device__ float g_embc[VV*EMBD];
__device__ float g_enc[BV*FF];
__device__ float g_initial[BVDF];
__device__ float g_state[BVDF];
__device__ float g_h[BVDF];          // h, later reused as msg
__device__ float g_score[BVD];
__device__ float g_agg[BV*FF];
__device__ float g_nw[BVD];
__device__ float g_attnin[BVD];
__device__ float g_norm[BVD];
__device__ float g_ns[BV*FF];
__device__ float g_dualvars[BV];
__device__ float g_fc[BB];
__device__ float g_dq[BVD/256];      // 1024 partials
__device__ float g_dd[BV/256];       // 64 partials

// ---------------- 1. emb row-normalize --------------------------------------
__global__ void k_emb(const float* __restrict__ emb){
    int warp = (blockIdx.x*blockDim.x + threadIdx.x) >> 5;
    int lane = threadIdx.x & 31;
    if (warp >= VV) return;
    float x = emb[warp*EMBD + lane];          // EMB==32 == warp size
    float s = x*x;
    #pragma unroll
    for (int o=16;o;o>>=1) s += __shfl_xor_sync(0xffffffffu, s, o);
    float nrm = sqrtf(s);
    float scale = fminf(1.0f, 1.0f / fmaxf(nrm, 1e-12f));
    g_embc[warp*EMBD + lane] = x*scale;
}

// ---------------- 2. encoder: concat(emb_c, feat) @ enc_W + b ---------------
__global__ void k_enc(const float* __restrict__ nf, const float* __restrict__ W,
                      const float* __restrict__ bvec){
    int node = blockIdx.x*4 + (threadIdx.x >> 6);
    int f = threadIdx.x & 63;
    int v = node & (VV-1);
    float acc = bvec[f];
    const float* ev = g_embc + v*EMBD;
    const float* nr = nf + node*FEAT;
    #pragma unroll
    for (int k=0;k<EMBD;k++) acc += ev[k]*W[k*FF+f];
    #pragma unroll
    for (int k=0;k<FEAT;k++) acc += nr[k]*W[(EMBD+k)*FF+f];
    g_enc[node*FF+f] = acc;
}

// ---------------- 3. initial = gather(enc, adj)*(1-mask); state=initial -----
__global__ void k_gather_init(const int* __restrict__ adj, const int* __restrict__ num_nodes){
    int t = blockIdx.x*256 + threadIdx.x;          // over BVD*16 float4 chunks
    int f4 = t & 15; int row = t >> 4;
    int node = row >> 4; int b = node >> 11;
    int a = adj[row];
    float m = (a == num_nodes[b]) ? 0.f : 1.f;
    float4 v = ((const float4*)(g_enc + ((b<<11)+a)*FF))[f4];
    v.x*=m; v.y*=m; v.z*=m; v.w*=m;
    ((float4*)(g_initial + row*FF))[f4] = v;
    ((float4*)(g_state   + row*FF))[f4] = v;
}

// ---------------- 4. h = tanh(state @ gat_W + gat_b), fused score ------------
// thread = row; weights broadcast from smem; row staged in XOR-swizzled smem.
#define GAT_SMEM ((64*64 + 256*64) * (int)sizeof(float))
__global__ void __launch_bounds__(256) k_gat(const float* __restrict__ W,
                                             const float* __restrict__ bvec,
                                             const float* __restrict__ gat_a){
    extern __shared__ float sh[];
    float* Ws   = sh;            // 64*64
    float* tile = sh + 64*64;    // 256*64 swizzled
    int t = threadIdx.x;
    size_t base = (size_t)blockIdx.x * 256;
    for (int i=t;i<64*64;i+=256) Ws[i] = W[i];
    for (int i=t;i<256*64;i+=256){
        int row = i>>6, k = i&63;
        tile[(row<<6) | (k ^ (row&31))] = g_state[base*FF + i];
    }
    __syncthreads();
    const float* srow = tile + (t<<6);
    int c = t & 31;
    size_t orow = (base + t) * FF;
    float sc = 0.f;
    for (int fo=0; fo<8; fo++){
        int f = fo*8;
        float acc[8];
        *(float4*)&acc[0] = __ldg((const float4*)(bvec+f));
        *(float4*)&acc[4] = __ldg((const float4*)(bvec+f+4));
        #pragma unroll 4
        for (int k=0;k<64;k++){
            float sk = srow[k ^ c];
            float w[8];
            *(float4*)&w[0] = *(const float4*)(Ws + k*64 + f);
            *(float4*)&w[4] = *(const float4*)(Ws + k*64 + f + 4);
            #pragma unroll
            for (int j=0;j<8;j++) acc[j] += sk*w[j];
        }
        float av[8];
        *(float4*)&av[0] = __ldg((const float4*)(gat_a+f));
        *(float4*)&av[4] = __ldg((const float4*)(gat_a+f+4));
        float hv[8];
        #pragma unroll
        for (int j=0;j<8;j++){ hv[j] = tanhf(acc[j]); sc += hv[j]*av[j]; }
        *(float4*)(g_h + orow + f)     = *(float4*)&hv[0];
        *(float4*)(g_h + orow + f + 4) = *(float4*)&hv[4];
    }
    g_score[base + t] = sc;
}

// ---------------- 5. softmax(D) over fused scores -> agg ---------------------
__global__ void k_attn(const int* __restrict__ adj, const int* __restrict__ num_nodes){
    int lane = threadIdx.x & 31;
    int node = blockIdx.x*8 + (threadIdx.x >> 5);
    int b = node >> 11;
    const float* hb = g_h + (size_t)node*DD*FF;
    float sc = -1e30f;
    if (lane < DD){
        int a = adj[node*DD+lane];
        sc = g_score[node*DD+lane] - ((a==num_nodes[b]) ? BIGC : 0.f);
    }
    float mx = sc;
    #pragma unroll
    for (int o=16;o;o>>=1) mx = fmaxf(mx, __shfl_xor_sync(0xffffffffu, mx, o));
    float e = (lane < DD) ? __expf(sc - mx) : 0.f;
    float sm = e;
    #pragma unroll
    for (int o=16;o;o>>=1) sm += __shfl_xor_sync(0xffffffffu, sm, o);
    float attn = e / sm;
    float a0=0.f, a1=0.f;
    #pragma unroll
    for (int d=0;d<DD;d++){
        float ad = __shfl_sync(0xffffffffu, attn, d);
        a0 += ad * hb[d*FF + lane];
        a1 += ad * hb[d*FF + lane + 32];
    }
    g_agg[node*FF + lane]      = a0;
    g_agg[node*FF + lane + 32] = a1;
}

// ---------------- 6. msg = gather(agg)*(1-mask) + initial  (into g_h) -------
__global__ void k_msg(const int* __restrict__ adj, const int* __restrict__ num_nodes){
    int t = blockIdx.x*256 + threadIdx.x;
    int f4 = t & 15; int row = t >> 4;
    int node = row >> 4; int b = node >> 11;
    int a = adj[row];
    float m = (a == num_nodes[b]) ? 0.f : 1.f;
    float4 g = ((const float4*)(g_agg + ((b<<11)+a)*FF))[f4];
    float4 ini = ((const float4*)(g_initial + row*FF))[f4];
    float4 o;
    o.x = g.x*m + ini.x; o.y = g.y*m + ini.y; o.z = g.z*m + ini.z; o.w = g.w*m + ini.w;
    ((float4*)(g_h + row*FF))[f4] = o;
}

// ---------------- 7. fused GRU: state = GRU(msg, state) ---------------------
// thread = row. Weights (both 64x192) in smem, broadcast reads. Row operands
// in XOR-swizzled smem tiles. 48 FFMA per k per thread -> FFMA-bound.
#define GRU_SMEM ((2*64*192 + 2*256*64) * (int)sizeof(float))
__global__ void __launch_bounds__(256, 1) k_gru(const float* __restrict__ Wx,
                                                const float* __restrict__ Wh,
                                                const float* __restrict__ bvec){
    extern __shared__ float sh[];
    float* Wxs = sh;                   // 64*192
    float* Whs = sh + 64*192;
    float* ms  = sh + 2*64*192;        // 256*64 swizzled
    float* ss  = ms + 256*64;
    int t = threadIdx.x;
    size_t base = (size_t)blockIdx.x * 256;
    for (int i=t;i<64*192;i+=256){ Wxs[i]=Wx[i]; Whs[i]=Wh[i]; }
    for (int i=t;i<256*64;i+=256){
        int row = i>>6, k = i&63;
        int sw = (row<<6) | (k ^ (row&31));
        ms[sw] = g_h[base*FF + i];
        ss[sw] = g_state[base*FF + i];
    }
    __syncthreads();
    const float* mrow = ms + (t<<6);
    const float* srow = ss + (t<<6);
    int c = t & 31;
    size_t orow = (base + t) * FF;
    for (int fo=0; fo<8; fo++){
        int f = fo*8;
        float x0[8],x1[8],x2[8],h0[8],h1[8],h2[8];
        #pragma unroll
        for (int j=0;j<8;j++){x0[j]=0.f;x1[j]=0.f;x2[j]=0.f;h0[j]=0.f;h1[j]=0.f;h2[j]=0.f;}
        #pragma unroll 4
        for (int k=0;k<64;k++){
            float mk = mrow[k ^ c];
            float sk = srow[k ^ c];
            const float* wxp = Wxs + k*192 + f;
            const float* whp = Whs + k*192 + f;
            float wa[8], wb[8], wcc[8], va[8], vb[8], vc[8];
            *(float4*)&wa[0]  = *(const float4*)(wxp);
            *(float4*)&wa[4]  = *(const float4*)(wxp+4);
            *(float4*)&wb[0]  = *(const float4*)(wxp+64);
            *(float4*)&wb[4]  = *(const float4*)(wxp+68);
            *(float4*)&wcc[0] = *(const float4*)(wxp+128);
            *(float4*)&wcc[4] = *(const float4*)(wxp+132);
            *(float4*)&va[0]  = *(const float4*)(whp);
            *(float4*)&va[4]  = *(const float4*)(whp+4);
            *(float4*)&vb[0]  = *(const float4*)(whp+64);
            *(float4*)&vb[4]  = *(const float4*)(whp+68);
            *(float4*)&vc[0]  = *(const float4*)(whp+128);
            *(float4*)&vc[4]  = *(const float4*)(whp+132);
            #pragma unroll
            for (int j=0;j<8;j++){
                x0[j] += mk*wa[j];  x1[j] += mk*wb[j];  x2[j] += mk*wcc[j];
                h0[j] += sk*va[j];  h1[j] += sk*vb[j];  h2[j] += sk*vc[j];
            }
        }
        float bz[8], br8[8], bh[8];
        *(float4*)&bz[0]  = __ldg((const float4*)(bvec+f));
        *(float4*)&bz[4]  = __ldg((const float4*)(bvec+f+4));
        *(float4*)&br8[0] = __ldg((const float4*)(bvec+64+f));
        *(float4*)&br8[4] = __ldg((const float4*)(bvec+64+f+4));
        *(float4*)&bh[0]  = __ldg((const float4*)(bvec+128+f));
        *(float4*)&bh[4]  = __ldg((const float4*)(bvec+128+f+4));
        float o[8];
        #pragma unroll
        for (int j=0;j<8;j++){
            float z    = 1.f/(1.f + __expf(-(x0[j] + bz[j]  + h0[j])));
            float r    = 1.f/(1.f + __expf(-(x1[j] + br8[j] + h1[j])));
            float cand = tanhf(x2[j] + bh[j] + r*h2[j]);
            float sold = srow[(f+j) ^ c];
            o[j] = z*sold + (1.f - z)*cand;
        }
        *(float4*)(g_state + orow + f)     = *(float4*)&o[0];
        *(float4*)(g_state + orow + f + 4) = *(float4*)&o[4];
    }
}

// ---------------- 8. generic 64->32->1 MLP head ------------------------------
__global__ void k_mlp(int mode, const float* __restrict__ W1, const float* __restrict__ b1,
                      const float* __restrict__ W2, const float* __restrict__ b2){
    __shared__ float S[128*65];
    __shared__ float W1s[64*32];
    __shared__ float b1s[32], W2s[32];
    const float* in = mode ? g_ns : g_state;
    float* out      = mode ? g_dualvars : g_nw;
    int t = threadIdx.x;
    int base = blockIdx.x*128;
    for (int i=t;i<2048;i+=128) W1s[i] = W1[i];
    if (t < 32){ b1s[t] = b1[t]; W2s[t] = W2[t]; }
    for (int c=0;c<64;c++){
        int lin = c*128 + t;
        int r = lin >> 6, k = lin & 63;
        S[r*65 + k] = in[(size_t)base*FF + lin];
    }
    __syncthreads();
    float acc[32];
    #pragma unroll
    for (int h=0;h<32;h++) acc[h] = b1s[h];
    const float* myrow = S + t*65;
    for (int k=0;k<64;k++){
        float s = myrow[k];
        #pragma unroll
        for (int h=0;h<32;h++) acc[h] += s*W1s[k*32+h];
    }
    float o = b2[0];
    #pragma unroll
    for (int h=0;h<32;h++) o += tanhf(acc[h])*W2s[h];
    out[base + t] = o;
}

// ---------------- 9. incoming-gather softmax ---------------------------------
__global__ void k_inattn(const int* __restrict__ in_idx, const int* __restrict__ inv_adj,
                         const int* __restrict__ num_nodes){
    int lane = threadIdx.x & 31;
    int node = blockIdx.x*8 + (threadIdx.x >> 5);
    int b = node >> 11;
    float sc = -1e30f;
    if (lane < DD){
        int idx = in_idx[node*DD + lane];
        float inc = g_nw[b*VD + idx];
        int ia = inv_adj[node*DD + lane];
        sc = inc - ((ia == num_nodes[b]) ? BIGC : 0.f);
    }
    float mx = sc;
    #pragma unroll
    for (int o=16;o;o>>=1) mx = fmaxf(mx, __shfl_xor_sync(0xffffffffu, mx, o));
    float e = (lane < DD) ? __expf(sc - mx) : 0.f;
    float sm = e;
    #pragma unroll
    for (int o=16;o;o>>=1) sm += __shfl_xor_sync(0xffffffffu, sm, o);
    if (lane < DD) g_attnin[node*DD + lane] = e / sm;
}

// ---------------- 10. rev-gather + masked softmax -> normalized --------------
__global__ void k_revnorm(const int* __restrict__ rev_idx, const int* __restrict__ adj,
                          const int* __restrict__ num_nodes){
    int lane = threadIdx.x & 31;
    int node = blockIdx.x*8 + (threadIdx.x >> 5);
    int b = node >> 11;
    float sc = -1e30f;
    if (lane < DD){
        int ridx = rev_idx[node*DD + lane];
        float val = g_attnin[b*VD + ridx];
        int a = adj[node*DD + lane];
        sc = val - ((a == num_nodes[b]) ? BIGC : 0.f);
    }
    float mx = sc;
    #pragma unroll
    for (int o=16;o;o>>=1) mx = fmaxf(mx, __shfl_xor_sync(0xffffffffu, mx, o));
    float e = (lane < DD) ? __expf(sc - mx) : 0.f;
    float sm = e;
    #pragma unroll
    for (int o=16;o;o>>=1) sm += __shfl_xor_sync(0xffffffffu, sm, o);
    if (lane < DD) g_norm[node*DD + lane] = e / sm;
}

// ---------------- 11. flow fixed-point, one block per batch ------------------
#define FLOW_SMEM ((VD + 2*VV) * (int)sizeof(float))
__global__ void k_flow(const float* __restrict__ demands, const int* __restrict__ inv_adj,
                       const int* __restrict__ in_idx, const int* __restrict__ num_nodes){
    extern __shared__ float sh[];
    float* flow = sh;             // VD
    float* infl = sh + VD;        // VV
    float* sup  = infl + VV;      // VV
    int b = blockIdx.x, t = threadIdx.x;
    int nn = num_nodes[b];
    for (int v=t; v<VV; v+=1024) sup[v] = fmaxf(-demands[b*VV + v], 0.f);
    __syncthreads();
    for (int i=t; i<VD; i+=1024) flow[i] = g_norm[b*VD + i] * sup[i>>4];
    __syncthreads();
    for (int it=0; it<10; it++){
        for (int v=t; v<VV; v+=1024){
            const int* ip = in_idx  + ((size_t)b*VV + v)*DD;
            const int* vp = inv_adj + ((size_t)b*VV + v)*DD;
            float s = 0.f;
            #pragma unroll
            for (int d=0;d<DD;d++){
                float m = (vp[d]==nn) ? 0.f : 1.f;
                s += flow[ip[d]] * m;
            }
            infl[v] = s;
        }
        __syncthreads();
        for (int i=t; i<VD; i+=1024) flow[i] = g_norm[b*VD + i] * (infl[i>>4] + sup[i>>4]);
        __syncthreads();
    }
    float c = 0.f;
    for (int i=t; i<VD; i+=1024) c += flow[i]*flow[i];
    infl[t] = c; __syncthreads();
    for (int s=512; s>0; s>>=1){ if (t < s) infl[t] += infl[t+s]; __syncthreads(); }
    if (t == 0) g_fc[b] = infl[0];
}

// ---------------- 12. node_states = state.sum(d) ------------------------------
__global__ void k_nodestates(){
    int t = blockIdx.x*256 + threadIdx.x;      // over BV*FF
    int f = t & 63; int node = t >> 6;
    float s = 0.f;
    #pragma unroll
    for (int d=0; d<DD; d++) s += g_state[((size_t)node*DD + d)*FF + f];
    g_ns[t] = s;
}

// ---------------- 13. dual iterations + quad cost partials --------------------
__global__ void k_dual(const int* __restrict__ adj, const int* __restrict__ num_nodes){
    __shared__ float red[256];
    int idx = blockIdx.x*256 + threadIdx.x;    // edge row
    int b = idx >> 15; int node = idx >> 4;
    int a = adj[idx]; int nn = num_nodes[b];
    float mask = (a==nn) ? 1.f : 0.f;
    float valid = 1.f - mask;
    float dv  = g_dualvars[node];
    float dtr = g_dualvars[(b<<11) + a] * valid;
    float dd  = dtr - mask*dv;
    float f = 0.f, ac = 0.f;
    #pragma unroll
    for (int i=0;i<10;i++){
        float g = 2.f*f + dd;
        ac = 0.9f*ac + 0.01f*g;
        f = fmaxf(f - ac, 0.f) * valid;
    }
    float c = f*f + dd*f;
    red[threadIdx.x] = c; __syncthreads();
    for (int s=128; s>0; s>>=1){ if (threadIdx.x < s) red[threadIdx.x] += red[threadIdx.x+s]; __syncthreads(); }
    if (threadIdx.x == 0) g_dq[blockIdx.x] = red[0];
}

// ---------------- 14. dual demand partials -----------------------------------
__global__ void k_dualdem(const float* __restrict__ demands){
    __shared__ float red[256];
    int idx = blockIdx.x*256 + threadIdx.x;    // node
    red[threadIdx.x] = g_dualvars[idx] * demands[idx];
    __syncthreads();
    for (int s=128; s>0; s>>=1){ if (threadIdx.x < s) red[threadIdx.x] += red[threadIdx.x+s]; __syncthreads(); }
    if (threadIdx.x == 0) g_dd[blockIdx.x] = red[0];
}

// ---------------- 15. finalize: out[b] = fc - dq + ddm -------------------------
__global__ void k_finalize(float* __restrict__ out){
    int w = threadIdx.x >> 5, lane = threadIdx.x & 31;
    if (w < BB){
        float dq = 0.f;
        #pragma unroll
        for (int i=0;i<4;i++) dq += g_dq[w*128 + lane + 32*i];
        float ddm = (lane < 8) ? g_dd[w*8 + lane] : 0.f;
        #pragma unroll
        for (int o=16;o;o>>=1){
            dq  += __shfl_xor_sync(0xffffffffu, dq,  o);
            ddm += __shfl_xor_sync(0xffffffffu, ddm, o);
        }
        if (lane == 0) out[w] = g_fc[w] - dq + ddm;
    }
}

// ---------------- launcher -----------------------------------------------------
extern "C" void kernel_launch(void* const* d_in, const int* in_sizes, int n_in,
                              void* d_out, int out_size){
    const float* node_features = (const float*)d_in[0];
    const float* demands       = (const float*)d_in[1];
    const float* emb           = (const float*)d_in[2];
    const float* enc_W         = (const float*)d_in[3];
    const float* enc_b         = (const float*)d_in[4];
    const float* gat_W         = (const float*)d_in[5];
    const float* gat_b         = (const float*)d_in[6];
    const float* gat_a         = (const float*)d_in[7];
    const float* gru_Wx        = (const float*)d_in[8];
    const float* gru_Wh        = (const float*)d_in[9];
    const float* gru_b         = (const float*)d_in[10];
    const float* dec_W1        = (const float*)d_in[11];
    const float* dec_b1        = (const float*)d_in[12];
    const float* dec_W2        = (const float*)d_in[13];
    const float* dec_b2        = (const float*)d_in[14];
    const float* dual_W1       = (const float*)d_in[15];
    const float* dual_b1       = (const float*)d_in[16];
    const float* dual_W2       = (const float*)d_in[17];
    const float* dual_b2       = (const float*)d_in[18];
    const int*   adj           = (const int*)d_in[19];
    const int*   inv_adj       = (const int*)d_in[20];
    const int*   in_idx        = (const int*)d_in[21];
    const int*   rev_idx       = (const int*)d_in[22];
    const int*   num_nodes     = (const int*)d_in[23];
    float* out = (float*)d_out;

    cudaFuncSetAttribute(k_gru,  cudaFuncAttributeMaxDynamicSharedMemorySize, GRU_SMEM);
    cudaFuncSetAttribute(k_gat,  cudaFuncAttributeMaxDynamicSharedMemorySize, GAT_SMEM);
    cudaFuncSetAttribute(k_flow, cudaFuncAttributeMaxDynamicSharedMemorySize, FLOW_SMEM);

    k_emb<<<VV*32/256, 256>>>(emb);
    k_enc<<<BV/4, 256>>>(node_features, enc_W, enc_b);
    k_gather_init<<<BVD*16/256, 256>>>(adj, num_nodes);

    for (int l=0; l<2; l++){
        k_gat <<<BVD/256, 256, GAT_SMEM>>>(gat_W, gat_b, gat_a);
        k_attn<<<BV/8,   256>>>(adj, num_nodes);
        k_msg <<<BVD*16/256, 256>>>(adj, num_nodes);
        k_gru <<<BVD/256, 256, GRU_SMEM>>>(gru_Wx, gru_Wh, gru_b);
    }

    // flow branch
    k_mlp<<<BVD/128, 128>>>(0, dec_W1, dec_b1, dec_W2, dec_b2);
    k_inattn <<<BV/8, 256>>>(in_idx, inv_adj, num_nodes);
    k_revnorm<<<BV/8, 256>>>(rev_idx, adj, num_nodes);
    k_flow<<<BB, 1024, FLOW_SMEM>>>(demands, inv_adj, in_idx, num_nodes);

    // dual branch
    k_nodestates<<<BV*FF/256, 256>>>();
    k_mlp<<<BV/128, 128>>>(1, dual_W1, dual_b1, dual_W2, dual_b2);
    k_dual<<<BVD/256, 256>>>(adj, num_nodes);
    k_dualdem<<<BV/256, 256>>>(demands);

    k_finalize<<<1, 256>>>(out);
}

// round 3
// speedup vs baseline: 11.4067x; 5.2495x over previous
#include <cuda_runtime.h>
#include <math.h>

#define BB 8
#define VV 2048
#define DD 16
#define FF 64
#define EMBD 32
#define HID 32
#define FEAT 16
#define BV (BB*VV)            // 16384
#define BVD (BV*DD)           // 262144
#define VD (VV*DD)            // 32768
#define NC (BV+1)             // 16385 classes (+1 global masked class)
#define NCPAD (65*256)        // 16640
#define BIGC 1e9f

// ---------------- scratch (device globals) -----------------------------------
__device__ float g_embc[VV*EMBD];
__device__ float g_enc[BV*FF];
__device__ float g_S[NCPAD*FF];      // per-class state
__device__ float g_H[NCPAD*FF];      // per-class tanh(state@W+b)
__device__ float g_sc[NCPAD];        // per-class gat score
__device__ float g_agg[BV*FF];       // per-node agg
__device__ float g_nwc[NCPAD];       // per-class decoder output
__device__ float g_nw[BVD];
__device__ float g_attnin[BVD];
__device__ float g_norm[BVD];
__device__ int   g_midx[BVD];        // mask-folded inflow index
__device__ float g_ns[BV*FF];
__device__ float g_dualvars[BV];
__device__ float g_fc[BB];
__device__ float g_dq[BVD/256];
__device__ float g_dd[BV/256];

// ---------------- 1. emb row-normalize ---------------------------------------
__global__ void k_emb(const float* __restrict__ emb){
    int warp = (blockIdx.x*blockDim.x + threadIdx.x) >> 5;
    int lane = threadIdx.x & 31;
    if (warp >= VV) return;
    float x = emb[warp*EMBD + lane];
    float s = x*x;
    #pragma unroll
    for (int o=16;o;o>>=1) s += __shfl_xor_sync(0xffffffffu, s, o);
    float nrm = sqrtf(s);
    float scale = fminf(1.0f, 1.0f / fmaxf(nrm, 1e-12f));
    g_embc[warp*EMBD + lane] = x*scale;
}

// ---------------- 2. encoder --------------------------------------------------
__global__ void k_enc(const float* __restrict__ nf, const float* __restrict__ W,
                      const float* __restrict__ bvec){
    int node = blockIdx.x*4 + (threadIdx.x >> 6);
    int f = threadIdx.x & 63;
    int v = node & (VV-1);
    float acc = bvec[f];
    const float* ev = g_embc + v*EMBD;
    const float* nr = nf + node*FEAT;
    #pragma unroll
    for (int k=0;k<EMBD;k++) acc += ev[k]*W[k*FF+f];
    #pragma unroll
    for (int k=0;k<FEAT;k++) acc += nr[k]*W[(EMBD+k)*FF+f];
    g_enc[node*FF+f] = acc;
}

// ---------------- 3. init S: classes 0..BV-1 = enc; rest = 0 ------------------
__global__ void k_initS(){
    int t = blockIdx.x*256 + threadIdx.x;           // float4 units, NCPAD*16 total
    float4 v = make_float4(0.f,0.f,0.f,0.f);
    if (t < BV*16) v = ((const float4*)g_enc)[t];
    ((float4*)g_S)[t] = v;
}

// ---------------- 3b. mask-folded inflow index --------------------------------
__global__ void k_midx(const int* __restrict__ in_idx, const int* __restrict__ inv_adj,
                       const int* __restrict__ num_nodes){
    int t = blockIdx.x*256 + threadIdx.x;           // BVD
    int b = t >> 15;
    g_midx[t] = (inv_adj[t]==num_nodes[b]) ? VD : in_idx[t];
}

// ---------------- 4. per-class GAT: H = tanh(S@W+b), sc = H.a -----------------
#define GAT_SMEM ((64*64 + 256*64) * (int)sizeof(float))
__global__ void __launch_bounds__(256) k_gat(const float* __restrict__ W,
                                             const float* __restrict__ bvec,
                                             const float* __restrict__ gat_a){
    extern __shared__ float sh[];
    float* Ws   = sh;
    float* tile = sh + 64*64;
    int t = threadIdx.x;
    size_t base = (size_t)blockIdx.x * 256;
    for (int i=t;i<64*64;i+=256) Ws[i] = W[i];
    for (int i=t;i<256*64;i+=256){
        int row = i>>6, k = i&63;
        tile[(row<<6) | (k ^ (row&31))] = g_S[base*FF + i];
    }
    __syncthreads();
    if (base + t >= NC) return;
    const float* srow = tile + (t<<6);
    int c = t & 31;
    size_t orow = (base + t) * FF;
    float sc = 0.f;
    for (int fo=0; fo<8; fo++){
        int f = fo*8;
        float acc[8];
        *(float4*)&acc[0] = __ldg((const float4*)(bvec+f));
        *(float4*)&acc[4] = __ldg((const float4*)(bvec+f+4));
        #pragma unroll 4
        for (int k=0;k<64;k++){
            float sk = srow[k ^ c];
            float w[8];
            *(float4*)&w[0] = *(const float4*)(Ws + k*64 + f);
            *(float4*)&w[4] = *(const float4*)(Ws + k*64 + f + 4);
            #pragma unroll
            for (int j=0;j<8;j++) acc[j] += sk*w[j];
        }
        float av[8];
        *(float4*)&av[0] = __ldg((const float4*)(gat_a+f));
        *(float4*)&av[4] = __ldg((const float4*)(gat_a+f+4));
        float hv[8];
        #pragma unroll
        for (int j=0;j<8;j++){ hv[j] = tanhf(acc[j]); sc += hv[j]*av[j]; }
        *(float4*)(g_H + orow + f)     = *(float4*)&hv[0];
        *(float4*)(g_H + orow + f + 4) = *(float4*)&hv[4];
    }
    g_sc[base + t] = sc;
}

// ---------------- 5. per-node softmax(D) + agg from class rows -----------------
__global__ void k_attnagg(const int* __restrict__ adj, const int* __restrict__ num_nodes){
    int lane = threadIdx.x & 31;
    int node = blockIdx.x*8 + (threadIdx.x >> 5);
    int b = node >> 11;
    int nn = num_nodes[b];
    int c = 0;
    float sc = -1e30f;
    if (lane < DD){
        int a = adj[node*DD+lane];
        bool m = (a==nn);
        c = m ? BV : ((b<<11)+a);
        sc = g_sc[c] - (m ? BIGC : 0.f);
    }
    float mx = sc;
    #pragma unroll
    for (int o=16;o;o>>=1) mx = fmaxf(mx, __shfl_xor_sync(0xffffffffu, mx, o));
    float e = (lane < DD) ? __expf(sc - mx) : 0.f;
    float sm = e;
    #pragma unroll
    for (int o=16;o;o>>=1) sm += __shfl_xor_sync(0xffffffffu, sm, o);
    float attn = e / sm;
    float a0=0.f, a1=0.f;
    #pragma unroll
    for (int d=0;d<DD;d++){
        float ad = __shfl_sync(0xffffffffu, attn, d);
        int  cd = __shfl_sync(0xffffffffu, c, d);
        const float* hr = g_H + (size_t)cd*FF;
        a0 += ad * hr[lane];
        a1 += ad * hr[lane + 32];
    }
    g_agg[node*FF + lane]      = a0;
    g_agg[node*FF + lane + 32] = a1;
}

// ---------------- 6. per-class GRU: S = GRU(agg+enc, S) ------------------------
#define GRU_SMEM ((2*64*192 + 2*256*64) * (int)sizeof(float))
__global__ void __launch_bounds__(256, 1) k_gru(const float* __restrict__ Wx,
                                                const float* __restrict__ Wh,
                                                const float* __restrict__ bvec){
    extern __shared__ float sh[];
    float* Wxs = sh;
    float* Whs = sh + 64*192;
    float* ms  = sh + 2*64*192;
    float* ss  = ms + 256*64;
    int t = threadIdx.x;
    size_t base = (size_t)blockIdx.x * 256;
    for (int i=t;i<64*192;i+=256){ Wxs[i]=Wx[i]; Whs[i]=Wh[i]; }
    for (int i=t;i<256*64;i+=256){
        int row = i>>6, k = i&63;
        size_t gr = base + row;
        int sw = (row<<6) | (k ^ (row&31));
        float mv = 0.f;
        if (gr < BV) mv = g_agg[gr*FF+k] + g_enc[gr*FF+k];
        ms[sw] = mv;
        ss[sw] = g_S[gr*FF + k];
    }
    __syncthreads();
    if (base + t >= NC) return;
    const float* mrow = ms + (t<<6);
    const float* srow = ss + (t<<6);
    int c = t & 31;
    size_t orow = (base + t) * FF;
    for (int fo=0; fo<8; fo++){
        int f = fo*8;
        float x0[8],x1[8],x2[8],h0[8],h1[8],h2[8];
        #pragma unroll
        for (int j=0;j<8;j++){x0[j]=0.f;x1[j]=0.f;x2[j]=0.f;h0[j]=0.f;h1[j]=0.f;h2[j]=0.f;}
        #pragma unroll 4
        for (int k=0;k<64;k++){
            float mk = mrow[k ^ c];
            float sk = srow[k ^ c];
            const float* wxp = Wxs + k*192 + f;
            const float* whp = Whs + k*192 + f;
            float wa[8], wb[8], wcc[8], va[8], vb[8], vc[8];
            *(float4*)&wa[0]  = *(const float4*)(wxp);
            *(float4*)&wa[4]  = *(const float4*)(wxp+4);
            *(float4*)&wb[0]  = *(const float4*)(wxp+64);
            *(float4*)&wb[4]  = *(const float4*)(wxp+68);
            *(float4*)&wcc[0] = *(const float4*)(wxp+128);
            *(float4*)&wcc[4] = *(const float4*)(wxp+132);
            *(float4*)&va[0]  = *(const float4*)(whp);
            *(float4*)&va[4]  = *(const float4*)(whp+4);
            *(float4*)&vb[0]  = *(const float4*)(whp+64);
            *(float4*)&vb[4]  = *(const float4*)(whp+68);
            *(float4*)&vc[0]  = *(const float4*)(whp+128);
            *(float4*)&vc[4]  = *(const float4*)(whp+132);
            #pragma unroll
            for (int j=0;j<8;j++){
                x0[j] += mk*wa[j];  x1[j] += mk*wb[j];  x2[j] += mk*wcc[j];
                h0[j] += sk*va[j];  h1[j] += sk*vb[j];  h2[j] += sk*vc[j];
            }
        }
        float bz[8], br8[8], bh[8];
        *(float4*)&bz[0]  = __ldg((const float4*)(bvec+f));
        *(float4*)&bz[4]  = __ldg((const float4*)(bvec+f+4));
        *(float4*)&br8[0] = __ldg((const float4*)(bvec+64+f));
        *(float4*)&br8[4] = __ldg((const float4*)(bvec+64+f+4));
        *(float4*)&bh[0]  = __ldg((const float4*)(bvec+128+f));
        *(float4*)&bh[4]  = __ldg((const float4*)(bvec+128+f+4));
        float o[8];
        #pragma unroll
        for (int j=0;j<8;j++){
            float z    = 1.f/(1.f + __expf(-(x0[j] + bz[j]  + h0[j])));
            float r    = 1.f/(1.f + __expf(-(x1[j] + br8[j] + h1[j])));
            float cand = tanhf(x2[j] + bh[j] + r*h2[j]);
            float sold = srow[(f+j) ^ c];
            o[j] = z*sold + (1.f - z)*cand;
        }
        *(float4*)(g_S + orow + f)     = *(float4*)&o[0];
        *(float4*)(g_S + orow + f + 4) = *(float4*)&o[4];
    }
}

// ---------------- 7. 64->32->1 MLP head ----------------------------------------
// mode 0: g_S (NC rows) -> g_nwc ; mode 1: g_ns (BV rows) -> g_dualvars
__global__ void k_mlp(int mode, const float* __restrict__ W1, const float* __restrict__ b1,
                      const float* __restrict__ W2, const float* __restrict__ b2){
    __shared__ float S[128*65];
    __shared__ float W1s[64*32];
    __shared__ float b1s[32], W2s[32];
    const float* in = mode ? g_ns : g_S;
    float* out      = mode ? g_dualvars : g_nwc;
    int nrows       = mode ? BV : NC;
    int t = threadIdx.x;
    int base = blockIdx.x*128;
    for (int i=t;i<2048;i+=128) W1s[i] = W1[i];
    if (t < 32){ b1s[t] = b1[t]; W2s[t] = W2[t]; }
    for (int c=0;c<64;c++){
        int lin = c*128 + t;
        int r = lin >> 6, k = lin & 63;
        S[r*65 + k] = in[(size_t)base*FF + lin];
    }
    __syncthreads();
    if (base + t >= nrows) return;
    float acc[32];
    #pragma unroll
    for (int h=0;h<32;h++) acc[h] = b1s[h];
    const float* myrow = S + t*65;
    for (int k=0;k<64;k++){
        float s = myrow[k];
        #pragma unroll
        for (int h=0;h<32;h++) acc[h] += s*W1s[k*32+h];
    }
    float o = b2[0];
    #pragma unroll
    for (int h=0;h<32;h++) o += tanhf(acc[h])*W2s[h];
    out[base + t] = o;
}

// ---------------- 8. expand class decoder value to edges ------------------------
__global__ void k_expand(const int* __restrict__ adj, const int* __restrict__ num_nodes){
    int t = blockIdx.x*256 + threadIdx.x;          // BVD
    int b = t >> 15;
    int a = adj[t];
    int c = (a==num_nodes[b]) ? BV : ((b<<11)+a);
    g_nw[t] = g_nwc[c];
}

// ---------------- 9. incoming-gather softmax ------------------------------------
__global__ void k_inattn(const int* __restrict__ in_idx, const int* __restrict__ inv_adj,
                         const int* __restrict__ num_nodes){
    int lane = threadIdx.x & 31;
    int node = blockIdx.x*8 + (threadIdx.x >> 5);
    int b = node >> 11;
    float sc = -1e30f;
    if (lane < DD){
        int idx = in_idx[node*DD + lane];
        float inc = g_nw[b*VD + idx];
        int ia = inv_adj[node*DD + lane];
        sc = inc - ((ia == num_nodes[b]) ? BIGC : 0.f);
    }
    float mx = sc;
    #pragma unroll
    for (int o=16;o;o>>=1) mx = fmaxf(mx, __shfl_xor_sync(0xffffffffu, mx, o));
    float e = (lane < DD) ? __expf(sc - mx) : 0.f;
    float sm = e;
    #pragma unroll
    for (int o=16;o;o>>=1) sm += __shfl_xor_sync(0xffffffffu, sm, o);
    if (lane < DD) g_attnin[node*DD + lane] = e / sm;
}

// ---------------- 10. rev-gather + masked softmax -> normalized ------------------
__global__ void k_revnorm(const int* __restrict__ rev_idx, const int* __restrict__ adj,
                          const int* __restrict__ num_nodes){
    int lane = threadIdx.x & 31;
    int node = blockIdx.x*8 + (threadIdx.x >> 5);
    int b = node >> 11;
    float sc = -1e30f;
    if (lane < DD){
        int ridx = rev_idx[node*DD + lane];
        float val = g_attnin[b*VD + ridx];
        int a = adj[node*DD + lane];
        sc = val - ((a == num_nodes[b]) ? BIGC : 0.f);
    }
    float mx = sc;
    #pragma unroll
    for (int o=16;o;o>>=1) mx = fmaxf(mx, __shfl_xor_sync(0xffffffffu, mx, o));
    float e = (lane < DD) ? __expf(sc - mx) : 0.f;
    float sm = e;
    #pragma unroll
    for (int o=16;o;o>>=1) sm += __shfl_xor_sync(0xffffffffu, sm, o);
    if (lane < DD) g_norm[node*DD + lane] = e / sm;
}

// ---------------- 11. flow fixed-point, one block per batch ----------------------
#define FLOW_SMEM ((VD + 32 + 2*VV) * (int)sizeof(float))
__global__ void k_flow(const float* __restrict__ demands, const int* __restrict__ num_nodes){
    extern __shared__ float sh[];
    float* flow = sh;             // VD+1 (slot VD = 0 sink for masked)
    float* infl = sh + VD + 32;   // VV
    float* sup  = infl + VV;      // VV
    int b = blockIdx.x, t = threadIdx.x;
    for (int v=t; v<VV; v+=1024) sup[v] = fmaxf(-demands[b*VV + v], 0.f);
    if (t == 0) flow[VD] = 0.f;
    __syncthreads();
    for (int i=t; i<VD; i+=1024) flow[i] = g_norm[b*VD + i] * sup[i>>4];
    __syncthreads();
    for (int it=0; it<10; it++){
        for (int v=t; v<VV; v+=1024){
            const int* ip = g_midx + ((size_t)b*VV + v)*DD;
            int idx[DD];
            #pragma unroll
            for (int d=0;d<DD;d+=4) *(int4*)&idx[d] = __ldg((const int4*)(ip+d));
            float s = 0.f;
            #pragma unroll
            for (int d=0;d<DD;d++) s += flow[idx[d]];
            infl[v] = s;
        }
        __syncthreads();
        for (int i=t; i<VD; i+=1024) flow[i] = g_norm[b*VD + i] * (infl[i>>4] + sup[i>>4]);
        __syncthreads();
    }
    float c = 0.f;
    for (int i=t; i<VD; i+=1024) c += flow[i]*flow[i];
    infl[t] = c; __syncthreads();
    for (int s=512; s>0; s>>=1){ if (t < s) infl[t] += infl[t+s]; __syncthreads(); }
    if (t == 0) g_fc[b] = infl[0];
}

// ---------------- 12. node_states = sum over d of class rows ----------------------
__global__ void k_nodestates(const int* __restrict__ adj, const int* __restrict__ num_nodes){
    int lane = threadIdx.x & 31;
    int node = blockIdx.x*8 + (threadIdx.x >> 5);
    int b = node >> 11;
    int nn = num_nodes[b];
    int c = 0;
    if (lane < DD){
        int a = adj[node*DD+lane];
        c = (a==nn) ? BV : ((b<<11)+a);
    }
    float s0=0.f, s1=0.f;
    #pragma unroll
    for (int d=0;d<DD;d++){
        int cd = __shfl_sync(0xffffffffu, c, d);
        const float* sr = g_S + (size_t)cd*FF;
        s0 += sr[lane];
        s1 += sr[lane + 32];
    }
    g_ns[node*FF + lane]      = s0;
    g_ns[node*FF + lane + 32] = s1;
}

// ---------------- 13. dual iterations + quad cost partials ------------------------
__global__ void k_dual(const int* __restrict__ adj, const int* __restrict__ num_nodes){
    __shared__ float red[256];
    int idx = blockIdx.x*256 + threadIdx.x;
    int b = idx >> 15; int node = idx >> 4;
    int a = adj[idx]; int nn = num_nodes[b];
    float mask = (a==nn) ? 1.f : 0.f;
    float valid = 1.f - mask;
    float dv  = g_dualvars[node];
    float dtr = g_dualvars[(b<<11) + a] * valid;
    float dd  = dtr - mask*dv;
    float f = 0.f, ac = 0.f;
    #pragma unroll
    for (int i=0;i<10;i++){
        float g = 2.f*f + dd;
        ac = 0.9f*ac + 0.01f*g;
        f = fmaxf(f - ac, 0.f) * valid;
    }
    float c = f*f + dd*f;
    red[threadIdx.x] = c; __syncthreads();
    for (int s=128; s>0; s>>=1){ if (threadIdx.x < s) red[threadIdx.x] += red[threadIdx.x+s]; __syncthreads(); }
    if (threadIdx.x == 0) g_dq[blockIdx.x] = red[0];
}

// ---------------- 14. dual demand partials -----------------------------------------
__global__ void k_dualdem(const float* __restrict__ demands){
    __shared__ float red[256];
    int idx = blockIdx.x*256 + threadIdx.x;
    red[threadIdx.x] = g_dualvars[idx] * demands[idx];
    __syncthreads();
    for (int s=128; s>0; s>>=1){ if (threadIdx.x < s) red[threadIdx.x] += red[threadIdx.x+s]; __syncthreads(); }
    if (threadIdx.x == 0) g_dd[blockIdx.x] = red[0];
}

// ---------------- 15. finalize ------------------------------------------------------
__global__ void k_finalize(float* __restrict__ out){
    int w = threadIdx.x >> 5, lane = threadIdx.x & 31;
    if (w < BB){
        float dq = 0.f;
        #pragma unroll
        for (int i=0;i<4;i++) dq += g_dq[w*128 + lane + 32*i];
        float ddm = (lane < 8) ? g_dd[w*8 + lane] : 0.f;
        #pragma unroll
        for (int o=16;o;o>>=1){
            dq  += __shfl_xor_sync(0xffffffffu, dq,  o);
            ddm += __shfl_xor_sync(0xffffffffu, ddm, o);
        }
        if (lane == 0) out[w] = g_fc[w] - dq + ddm;
    }
}

// ---------------- launcher -----------------------------------------------------------
extern "C" void kernel_launch(void* const* d_in, const int* in_sizes, int n_in,
                              void* d_out, int out_size){
    const float* node_features = (const float*)d_in[0];
    const float* demands       = (const float*)d_in[1];
    const float* emb           = (const float*)d_in[2];
    const float* enc_W         = (const float*)d_in[3];
    const float* enc_b         = (const float*)d_in[4];
    const float* gat_W         = (const float*)d_in[5];
    const float* gat_b         = (const float*)d_in[6];
    const float* gat_a         = (const float*)d_in[7];
    const float* gru_Wx        = (const float*)d_in[8];
    const float* gru_Wh        = (const float*)d_in[9];
    const float* gru_b         = (const float*)d_in[10];
    const float* dec_W1        = (const float*)d_in[11];
    const float* dec_b1        = (const float*)d_in[12];
    const float* dec_W2        = (const float*)d_in[13];
    const float* dec_b2        = (const float*)d_in[14];
    const float* dual_W1       = (const float*)d_in[15];
    const float* dual_b1       = (const float*)d_in[16];
    const float* dual_W2       = (const float*)d_in[17];
    const float* dual_b2       = (const float*)d_in[18];
    const int*   adj           = (const int*)d_in[19];
    const int*   inv_adj       = (const int*)d_in[20];
    const int*   in_idx        = (const int*)d_in[21];
    const int*   rev_idx       = (const int*)d_in[22];
    const int*   num_nodes     = (const int*)d_in[23];
    float* out = (float*)d_out;

    cudaFuncSetAttribute(k_gru,  cudaFuncAttributeMaxDynamicSharedMemorySize, GRU_SMEM);
    cudaFuncSetAttribute(k_gat,  cudaFuncAttributeMaxDynamicSharedMemorySize, GAT_SMEM);
    cudaFuncSetAttribute(k_flow, cudaFuncAttributeMaxDynamicSharedMemorySize, FLOW_SMEM);

    k_emb<<<VV*32/256, 256>>>(emb);
    k_enc<<<BV/4, 256>>>(node_features, enc_W, enc_b);
    k_initS<<<NCPAD*16/256, 256>>>();
    k_midx<<<BVD/256, 256>>>(in_idx, inv_adj, num_nodes);

    for (int l=0; l<2; l++){
        k_gat    <<<NCPAD/256, 256, GAT_SMEM>>>(gat_W, gat_b, gat_a);
        k_attnagg<<<BV/8, 256>>>(adj, num_nodes);
        k_gru    <<<NCPAD/256, 256, GRU_SMEM>>>(gru_Wx, gru_Wh, gru_b);
    }

    // flow branch
    k_mlp<<<(NC+127)/128, 128>>>(0, dec_W1, dec_b1, dec_W2, dec_b2);
    k_expand <<<BVD/256, 256>>>(adj, num_nodes);
    k_inattn <<<BV/8, 256>>>(in_idx, inv_adj, num_nodes);
    k_revnorm<<<BV/8, 256>>>(rev_idx, adj, num_nodes);
    k_flow<<<BB, 1024, FLOW_SMEM>>>(demands, num_nodes);

    // dual branch
    k_nodestates<<<BV/8, 256>>>(adj, num_nodes);
    k_mlp<<<BV/128, 128>>>(1, dual_W1, dual_b1, dual_W2, dual_b2);
    k_dual<<<BVD/256, 256>>>(adj, num_nodes);
    k_dualdem<<<BV/256, 256>>>(demands);

    k_finalize<<<1, 256>>>(out);
}

// round 4
// speedup vs baseline: 18.5732x; 1.6283x over previous
#include <cuda_runtime.h>
#include <math.h>

#define BB 8
#define VV 2048
#define DD 16
#define FF 64
#define EMBD 32
#define HID 32
#define FEAT 16
#define BV (BB*VV)            // 16384
#define BVD (BV*DD)           // 262144
#define VD (VV*DD)            // 32768
#define NC (BV+1)             // 16385 classes (+1 global masked class)
#define NCPAD (65*256)        // 16640
#define BIGC 1e9f

// ---------------- packed f32x2 helpers ----------------------------------------
__device__ __forceinline__ unsigned long long pack2(float lo, float hi){
    unsigned long long r;
    asm("mov.b64 %0, {%1, %2};" : "=l"(r) : "f"(lo), "f"(hi));
    return r;
}
__device__ __forceinline__ void unpack2(unsigned long long v, float& lo, float& hi){
    asm("mov.b64 {%0, %1}, %2;" : "=f"(lo), "=f"(hi) : "l"(v));
}
__device__ __forceinline__ void fma2(unsigned long long& d, unsigned long long a, unsigned long long b){
    asm("fma.rn.f32x2 %0, %1, %2, %0;" : "+l"(d) : "l"(a), "l"(b));
}

// ---------------- scratch (device globals) -----------------------------------
__device__ float g_enc[BV*FF];
__device__ float g_S[NCPAD*FF];      // per-class state
__device__ float g_H[NCPAD*FF];      // per-class tanh(state@W+b)
__device__ float g_sc[NCPAD];        // per-class gat score
__device__ float g_agg[BV*FF];       // per-node agg
__device__ float g_nwc[NCPAD];       // per-class decoder output
__device__ float g_attnin[BVD];
__device__ float g_norm[BVD];
__device__ float g_ns[BV*FF];
__device__ float g_dualvars[BV];
__device__ float g_fc[BB];
__device__ float g_dq[BVD/256];

// ---------------- 1. fused emb-normalize + encoder + S init -------------------
// blocks 0..4095: 4 nodes each. blocks 4096..4111: zero tail of g_S.
__global__ void k_enc(const float* __restrict__ nf, const float* __restrict__ emb,
                      const float* __restrict__ W, const float* __restrict__ bvec){
    if (blockIdx.x >= BV/4){
        int i = (blockIdx.x - BV/4)*256 + threadIdx.x;     // float4 units, 4096 total
        ((float4*)(g_S + (size_t)BV*FF))[i] = make_float4(0.f,0.f,0.f,0.f);
        return;
    }
    __shared__ float sEmb[4*EMBD];
    int t = threadIdx.x;
    int w = t >> 5, lane = t & 31;
    if (w < 4){
        int v = (blockIdx.x*4 + w) & (VV-1);
        float x = emb[v*EMBD + lane];
        float s = x*x;
        #pragma unroll
        for (int o=16;o;o>>=1) s += __shfl_xor_sync(0xffffffffu, s, o);
        float nrm = sqrtf(s);
        float scale = fminf(1.0f, 1.0f / fmaxf(nrm, 1e-12f));
        sEmb[w*EMBD + lane] = x*scale;
    }
    __syncthreads();
    int nl = t >> 6, f = t & 63;
    int node = blockIdx.x*4 + nl;
    float acc = bvec[f];
    const float* ev = sEmb + nl*EMBD;
    const float* nr = nf + node*FEAT;
    #pragma unroll
    for (int k=0;k<EMBD;k++) acc += ev[k]*W[k*FF+f];
    #pragma unroll
    for (int k=0;k<FEAT;k++) acc += nr[k]*W[(EMBD+k)*FF+f];
    g_enc[node*FF+f] = acc;
    g_S[(size_t)node*FF+f] = acc;
}

// ---------------- 2. per-class GAT: H = tanh(S@W+b), sc = H.a ------------------
// 128 rows/block, 256 threads: 2 threads per row, each 4 f-chunks of 8.
#define GAT_SMEM ((64*64 + 128*64) * (int)sizeof(float))
__global__ void __launch_bounds__(256) k_gat(const float* __restrict__ W,
                                             const float* __restrict__ bvec,
                                             const float* __restrict__ gat_a){
    extern __shared__ float sh[];
    float* Ws   = sh;                 // 64*64
    float* tile = sh + 64*64;         // 128*64 swizzled
    __shared__ float scpart[256];
    int t = threadIdx.x;
    size_t base = (size_t)blockIdx.x * 128;
    for (int i=t;i<64*64;i+=256) Ws[i] = W[i];
    for (int i=t;i<128*64;i+=256){
        int row = i>>6, k = i&63;
        tile[(row<<6) | (k ^ (row&31))] = g_S[base*FF + i];
    }
    __syncthreads();
    int row = t & 127, half = t >> 7;
    const float* srow = tile + (row<<6);
    int c = row & 31;
    size_t orow = (base + row) * FF;
    bool live = (base + row) < NC;
    float sc = 0.f;
    for (int fo=0; fo<4; fo++){
        int f = (half*4 + fo)*8;
        unsigned long long acc[4];
        {
            float b8[8];
            *(float4*)&b8[0] = __ldg((const float4*)(bvec+f));
            *(float4*)&b8[4] = __ldg((const float4*)(bvec+f+4));
            #pragma unroll
            for (int j=0;j<4;j++) acc[j] = pack2(b8[2*j], b8[2*j+1]);
        }
        #pragma unroll 4
        for (int k=0;k<64;k++){
            float skf = srow[k ^ c];
            unsigned long long sk2 = pack2(skf, skf);
            const ulonglong2* wp = (const ulonglong2*)(Ws + k*64 + f);
            ulonglong2 w01 = wp[0], w23 = wp[1];
            fma2(acc[0], w01.x, sk2);
            fma2(acc[1], w01.y, sk2);
            fma2(acc[2], w23.x, sk2);
            fma2(acc[3], w23.y, sk2);
        }
        float av[8], hv[8];
        *(float4*)&av[0] = __ldg((const float4*)(gat_a+f));
        *(float4*)&av[4] = __ldg((const float4*)(gat_a+f+4));
        #pragma unroll
        for (int j=0;j<4;j++){
            float a0,a1; unpack2(acc[j], a0, a1);
            hv[2*j]   = tanhf(a0);
            hv[2*j+1] = tanhf(a1);
            sc += hv[2*j]*av[2*j] + hv[2*j+1]*av[2*j+1];
        }
        if (live){
            *(float4*)(g_H + orow + f)     = *(float4*)&hv[0];
            *(float4*)(g_H + orow + f + 4) = *(float4*)&hv[4];
        }
    }
    scpart[t] = sc;
    __syncthreads();
    if (t < 128 && (base + t) < NC) g_sc[base + t] = scpart[t] + scpart[t+128];
}

// ---------------- 3. per-node softmax(D) + agg from class rows ------------------
__global__ void k_attnagg(const int* __restrict__ adj, const int* __restrict__ num_nodes){
    int lane = threadIdx.x & 31;
    int node = blockIdx.x*8 + (threadIdx.x >> 5);
    int b = node >> 11;
    int nn = num_nodes[b];
    int c = 0;
    float sc = -1e30f;
    if (lane < DD){
        int a = adj[node*DD+lane];
        bool m = (a==nn);
        c = m ? BV : ((b<<11)+a);
        sc = g_sc[c] - (m ? BIGC : 0.f);
    }
    float mx = sc;
    #pragma unroll
    for (int o=16;o;o>>=1) mx = fmaxf(mx, __shfl_xor_sync(0xffffffffu, mx, o));
    float e = (lane < DD) ? __expf(sc - mx) : 0.f;
    float sm = e;
    #pragma unroll
    for (int o=16;o;o>>=1) sm += __shfl_xor_sync(0xffffffffu, sm, o);
    float attn = e / sm;
    float a0=0.f, a1=0.f;
    #pragma unroll
    for (int d=0;d<DD;d++){
        float ad = __shfl_sync(0xffffffffu, attn, d);
        int  cd = __shfl_sync(0xffffffffu, c, d);
        const float* hr = g_H + (size_t)cd*FF;
        a0 += ad * hr[lane];
        a1 += ad * hr[lane + 32];
    }
    g_agg[node*FF + lane]      = a0;
    g_agg[node*FF + lane + 32] = a1;
}

// ---------------- 4. per-class GRU: S = GRU(agg+enc, S) -------------------------
// 128 rows/block, 256 threads: 2 per row, 4 f-chunks each. f32x2 FMA.
#define GRU_SMEM ((2*64*192 + 2*128*64) * (int)sizeof(float))
__global__ void __launch_bounds__(256, 1) k_gru(const float* __restrict__ Wx,
                                                const float* __restrict__ Wh,
                                                const float* __restrict__ bvec){
    extern __shared__ float sh[];
    float* Wxs = sh;                   // 64*192
    float* Whs = sh + 64*192;
    float* ms  = sh + 2*64*192;        // 128*64 swizzled
    float* ss  = ms + 128*64;
    int t = threadIdx.x;
    size_t base = (size_t)blockIdx.x * 128;
    {
        const float4* wx4 = (const float4*)Wx;
        const float4* wh4 = (const float4*)Wh;
        float4* wxs4 = (float4*)Wxs;
        float4* whs4 = (float4*)Whs;
        for (int i=t;i<64*192/4;i+=256){ wxs4[i]=wx4[i]; whs4[i]=wh4[i]; }
    }
    for (int i=t;i<128*64;i+=256){
        int row = i>>6, k = i&63;
        size_t gr = base + row;
        int sw = (row<<6) | (k ^ (row&31));
        float mv = 0.f;
        if (gr < BV) mv = g_agg[gr*FF+k] + g_enc[gr*FF+k];
        ms[sw] = mv;
        ss[sw] = g_S[gr*FF + k];
    }
    __syncthreads();
    int row = t & 127, half = t >> 7;
    if (base + row >= NC) return;
    const float* mrow = ms + (row<<6);
    const float* srow = ss + (row<<6);
    int c = row & 31;
    size_t orow = (base + row) * FF;
    for (int fo=0; fo<4; fo++){
        int f = (half*4 + fo)*8;
        unsigned long long X0[4],X1[4],X2[4],H0[4],H1[4],H2[4];
        #pragma unroll
        for (int j=0;j<4;j++){X0[j]=0ull;X1[j]=0ull;X2[j]=0ull;H0[j]=0ull;H1[j]=0ull;H2[j]=0ull;}
        #pragma unroll 2
        for (int k=0;k<64;k++){
            float mkf = mrow[k ^ c];
            float skf = srow[k ^ c];
            unsigned long long mk2 = pack2(mkf, mkf);
            unsigned long long sk2 = pack2(skf, skf);
            const float* wxp = Wxs + k*192 + f;
            const float* whp = Whs + k*192 + f;
            ulonglong2 xa = ((const ulonglong2*)(wxp))[0];
            ulonglong2 xa2= ((const ulonglong2*)(wxp+4))[0];
            ulonglong2 xb = ((const ulonglong2*)(wxp+64))[0];
            ulonglong2 xb2= ((const ulonglong2*)(wxp+68))[0];
            ulonglong2 xc = ((const ulonglong2*)(wxp+128))[0];
            ulonglong2 xc2= ((const ulonglong2*)(wxp+132))[0];
            ulonglong2 ha = ((const ulonglong2*)(whp))[0];
            ulonglong2 ha2= ((const ulonglong2*)(whp+4))[0];
            ulonglong2 hb = ((const ulonglong2*)(whp+64))[0];
            ulonglong2 hb2= ((const ulonglong2*)(whp+68))[0];
            ulonglong2 hc = ((const ulonglong2*)(whp+128))[0];
            ulonglong2 hc2= ((const ulonglong2*)(whp+132))[0];
            fma2(X0[0], xa.x, mk2);  fma2(X0[1], xa.y, mk2);
            fma2(X0[2], xa2.x, mk2); fma2(X0[3], xa2.y, mk2);
            fma2(X1[0], xb.x, mk2);  fma2(X1[1], xb.y, mk2);
            fma2(X1[2], xb2.x, mk2); fma2(X1[3], xb2.y, mk2);
            fma2(X2[0], xc.x, mk2);  fma2(X2[1], xc.y, mk2);
            fma2(X2[2], xc2.x, mk2); fma2(X2[3], xc2.y, mk2);
            fma2(H0[0], ha.x, sk2);  fma2(H0[1], ha.y, sk2);
            fma2(H0[2], ha2.x, sk2); fma2(H0[3], ha2.y, sk2);
            fma2(H1[0], hb.x, sk2);  fma2(H1[1], hb.y, sk2);
            fma2(H1[2], hb2.x, sk2); fma2(H1[3], hb2.y, sk2);
            fma2(H2[0], hc.x, sk2);  fma2(H2[1], hc.y, sk2);
            fma2(H2[2], hc2.x, sk2); fma2(H2[3], hc2.y, sk2);
        }
        float bz[8], br8[8], bh[8], o[8];
        *(float4*)&bz[0]  = __ldg((const float4*)(bvec+f));
        *(float4*)&bz[4]  = __ldg((const float4*)(bvec+f+4));
        *(float4*)&br8[0] = __ldg((const float4*)(bvec+64+f));
        *(float4*)&br8[4] = __ldg((const float4*)(bvec+64+f+4));
        *(float4*)&bh[0]  = __ldg((const float4*)(bvec+128+f));
        *(float4*)&bh[4]  = __ldg((const float4*)(bvec+128+f+4));
        #pragma unroll
        for (int j=0;j<4;j++){
            float x0a,x0b,x1a,x1b,x2a,x2b,h0a,h0b,h1a,h1b,h2a,h2b;
            unpack2(X0[j],x0a,x0b); unpack2(X1[j],x1a,x1b); unpack2(X2[j],x2a,x2b);
            unpack2(H0[j],h0a,h0b); unpack2(H1[j],h1a,h1b); unpack2(H2[j],h2a,h2b);
            {
                float z    = 1.f/(1.f + __expf(-(x0a + bz[2*j]  + h0a)));
                float r    = 1.f/(1.f + __expf(-(x1a + br8[2*j] + h1a)));
                float cand = tanhf(x2a + bh[2*j] + r*h2a);
                float sold = srow[(f+2*j) ^ c];
                o[2*j] = z*sold + (1.f - z)*cand;
            }
            {
                float z    = 1.f/(1.f + __expf(-(x0b + bz[2*j+1]  + h0b)));
                float r    = 1.f/(1.f + __expf(-(x1b + br8[2*j+1] + h1b)));
                float cand = tanhf(x2b + bh[2*j+1] + r*h2b);
                float sold = srow[(f+2*j+1) ^ c];
                o[2*j+1] = z*sold + (1.f - z)*cand;
            }
        }
        *(float4*)(g_S + orow + f)     = *(float4*)&o[0];
        *(float4*)(g_S + orow + f + 4) = *(float4*)&o[4];
    }
}

// ---------------- 5. 64->32->1 MLP head -------------------------------------------
__global__ void k_mlp(int mode, const float* __restrict__ W1, const float* __restrict__ b1,
                      const float* __restrict__ W2, const float* __restrict__ b2){
    __shared__ float S[128*65];
    __shared__ float W1s[64*32];
    __shared__ float b1s[32], W2s[32];
    const float* in = mode ? g_ns : g_S;
    float* out      = mode ? g_dualvars : g_nwc;
    int nrows       = mode ? BV : NC;
    int t = threadIdx.x;
    int base = blockIdx.x*128;
    for (int i=t;i<2048;i+=128) W1s[i] = W1[i];
    if (t < 32){ b1s[t] = b1[t]; W2s[t] = W2[t]; }
    for (int c=0;c<64;c++){
        int lin = c*128 + t;
        int r = lin >> 6, k = lin & 63;
        S[r*65 + k] = in[(size_t)base*FF + lin];
    }
    __syncthreads();
    if (base + t >= nrows) return;
    float acc[32];
    #pragma unroll
    for (int h=0;h<32;h++) acc[h] = b1s[h];
    const float* myrow = S + t*65;
    for (int k=0;k<64;k++){
        float s = myrow[k];
        #pragma unroll
        for (int h=0;h<32;h++) acc[h] += s*W1s[k*32+h];
    }
    float o = b2[0];
    #pragma unroll
    for (int h=0;h<32;h++) o += tanhf(acc[h])*W2s[h];
    out[base + t] = o;
}

// ---------------- 6. incoming-gather softmax (expand fused) -----------------------
__global__ void k_inattn(const int* __restrict__ in_idx, const int* __restrict__ inv_adj,
                         const int* __restrict__ adj, const int* __restrict__ num_nodes){
    int lane = threadIdx.x & 31;
    int node = blockIdx.x*8 + (threadIdx.x >> 5);
    int b = node >> 11;
    int nn = num_nodes[b];
    float sc = -1e30f;
    if (lane < DD){
        int idx = in_idx[node*DD + lane];
        int a2 = adj[b*VD + idx];
        float inc = g_nwc[(a2==nn) ? BV : ((b<<11)+a2)];
        int ia = inv_adj[node*DD + lane];
        sc = inc - ((ia == nn) ? BIGC : 0.f);
    }
    float mx = sc;
    #pragma unroll
    for (int o=16;o;o>>=1) mx = fmaxf(mx, __shfl_xor_sync(0xffffffffu, mx, o));
    float e = (lane < DD) ? __expf(sc - mx) : 0.f;
    float sm = e;
    #pragma unroll
    for (int o=16;o;o>>=1) sm += __shfl_xor_sync(0xffffffffu, sm, o);
    if (lane < DD) g_attnin[node*DD + lane] = e / sm;
}

// ---------------- 7. rev-gather + masked softmax -> normalized ---------------------
__global__ void k_revnorm(const int* __restrict__ rev_idx, const int* __restrict__ adj,
                          const int* __restrict__ num_nodes){
    int lane = threadIdx.x & 31;
    int node = blockIdx.x*8 + (threadIdx.x >> 5);
    int b = node >> 11;
    float sc = -1e30f;
    if (lane < DD){
        int ridx = rev_idx[node*DD + lane];
        float val = g_attnin[b*VD + ridx];
        int a = adj[node*DD + lane];
        sc = val - ((a == num_nodes[b]) ? BIGC : 0.f);
    }
    float mx = sc;
    #pragma unroll
    for (int o=16;o;o>>=1) mx = fmaxf(mx, __shfl_xor_sync(0xffffffffu, mx, o));
    float e = (lane < DD) ? __expf(sc - mx) : 0.f;
    float sm = e;
    #pragma unroll
    for (int o=16;o;o>>=1) sm += __shfl_xor_sync(0xffffffffu, sm, o);
    if (lane < DD) g_norm[node*DD + lane] = e / sm;
}

// ---------------- 8. flow fixed-point on node vector t, 1 block/batch ---------------
// flow = norm (x) expand(t). t_{k+1}[v] = sup[v] + sum_d w[v,d]*t[src[v,d]].
#define FLOW_SMEM ((VD + VV + VV + 1024) * (int)sizeof(float))
__global__ void __launch_bounds__(1024) k_flow(const float* __restrict__ demands,
                                               const int* __restrict__ inv_adj,
                                               const int* __restrict__ in_idx,
                                               const int* __restrict__ num_nodes){
    extern __shared__ float sh[];
    float* wT  = sh;              // [DD][VV] transposed weights
    float* ts  = sh + VD;         // VV
    float* sup = ts + VV;         // VV
    float* red = sup + VV;        // 1024
    int b = blockIdx.x, t = threadIdx.x;
    int nn = num_nodes[b];
    unsigned int sp[2][8];        // packed source node indices (16-bit)
    float nsq[2];
    #pragma unroll
    for (int n=0;n<2;n++){
        int v = t + n*1024;
        size_t ebase = ((size_t)b*VV + v)*DD;
        int ia[DD], m[DD];
        #pragma unroll
        for (int d=0;d<DD;d+=4){
            *(int4*)&ia[d] = __ldg((const int4*)(inv_adj + ebase + d));
            *(int4*)&m[d]  = __ldg((const int4*)(in_idx  + ebase + d));
        }
        float nrm[DD];
        #pragma unroll
        for (int d=0;d<DD;d+=4)
            *(float4*)&nrm[d] = __ldg((const float4*)(g_norm + (size_t)b*VD + v*DD + d));
        float q = 0.f;
        #pragma unroll
        for (int d=0;d<DD;d++) q += nrm[d]*nrm[d];
        nsq[n] = q;
        #pragma unroll
        for (int d=0;d<DD;d++){
            float wv = (ia[d]==nn) ? 0.f : g_norm[(size_t)b*VD + m[d]];
            wT[d*VV + v] = wv;
            int sv = m[d] >> 4;
            if ((d&1)==0) sp[n][d>>1] = (unsigned int)sv;
            else          sp[n][d>>1] |= ((unsigned int)sv) << 16;
        }
        float s = fmaxf(-demands[b*VV + v], 0.f);
        sup[v] = s;
        ts[v] = s;
    }
    __syncthreads();
    for (int it=0; it<10; it++){
        float acc[2] = {0.f, 0.f};
        #pragma unroll
        for (int n=0;n<2;n++){
            int v = t + n*1024;
            #pragma unroll
            for (int d=0;d<DD;d++){
                unsigned int pk = sp[n][d>>1];
                int sv = (d&1) ? (pk>>16) : (pk & 0xffff);
                acc[n] += wT[d*VV + v] * ts[sv];
            }
        }
        __syncthreads();
        ts[t]        = sup[t]        + acc[0];
        ts[t + 1024] = sup[t + 1024] + acc[1];
        __syncthreads();
    }
    float c = nsq[0]*ts[t]*ts[t] + nsq[1]*ts[t+1024]*ts[t+1024];
    red[t] = c; __syncthreads();
    for (int s=512; s>0; s>>=1){ if (t < s) red[t] += red[t+s]; __syncthreads(); }
    if (t == 0) g_fc[b] = red[0];
}

// ---------------- 9. node_states = sum over d of class rows -------------------------
__global__ void k_nodestates(const int* __restrict__ adj, const int* __restrict__ num_nodes){
    int lane = threadIdx.x & 31;
    int node = blockIdx.x*8 + (threadIdx.x >> 5);
    int b = node >> 11;
    int nn = num_nodes[b];
    int c = 0;
    if (lane < DD){
        int a = adj[node*DD+lane];
        c = (a==nn) ? BV : ((b<<11)+a);
    }
    float s0=0.f, s1=0.f;
    #pragma unroll
    for (int d=0;d<DD;d++){
        int cd = __shfl_sync(0xffffffffu, c, d);
        const float* sr = g_S + (size_t)cd*FF;
        s0 += sr[lane];
        s1 += sr[lane + 32];
    }
    g_ns[node*FF + lane]      = s0;
    g_ns[node*FF + lane + 32] = s1;
}

// ---------------- 10. dual iterations + quad cost + demand fold ----------------------
__global__ void k_dual(const int* __restrict__ adj, const int* __restrict__ num_nodes,
                       const float* __restrict__ demands){
    __shared__ float red[256];
    int idx = blockIdx.x*256 + threadIdx.x;
    int b = idx >> 15; int node = idx >> 4;
    int a = adj[idx]; int nn = num_nodes[b];
    float mask = (a==nn) ? 1.f : 0.f;
    float valid = 1.f - mask;
    float dv  = g_dualvars[node];
    float dtr = g_dualvars[(b<<11) + a] * valid;
    float dd  = dtr - mask*dv;
    float f = 0.f, ac = 0.f;
    #pragma unroll
    for (int i=0;i<10;i++){
        float g = 2.f*f + dd;
        ac = 0.9f*ac + 0.01f*g;
        f = fmaxf(f - ac, 0.f) * valid;
    }
    float c = f*f + dd*f;
    if ((idx & 15) == 0) c -= dv * demands[node];     // fold dual_demand (once per node)
    red[threadIdx.x] = c; __syncthreads();
    for (int s=128; s>0; s>>=1){ if (threadIdx.x < s) red[threadIdx.x] += red[threadIdx.x+s]; __syncthreads(); }
    if (threadIdx.x == 0) g_dq[blockIdx.x] = red[0];
}

// ---------------- 11. finalize: out[b] = fc - sum(dq partials) ------------------------
__global__ void k_finalize(float* __restrict__ out){
    int w = threadIdx.x >> 5, lane = threadIdx.x & 31;
    if (w < BB){
        float dq = 0.f;
        #pragma unroll
        for (int i=0;i<4;i++) dq += g_dq[w*128 + lane + 32*i];
        #pragma unroll
        for (int o=16;o;o>>=1) dq += __shfl_xor_sync(0xffffffffu, dq, o);
        if (lane == 0) out[w] = g_fc[w] - dq;
    }
}

// ---------------- launcher -------------------------------------------------------------
extern "C" void kernel_launch(void* const* d_in, const int* in_sizes, int n_in,
                              void* d_out, int out_size){
    const float* node_features = (const float*)d_in[0];
    const float* demands       = (const float*)d_in[1];
    const float* emb           = (const float*)d_in[2];
    const float* enc_W         = (const float*)d_in[3];
    const float* enc_b         = (const float*)d_in[4];
    const float* gat_W         = (const float*)d_in[5];
    const float* gat_b         = (const float*)d_in[6];
    const float* gat_a         = (const float*)d_in[7];
    const float* gru_Wx        = (const float*)d_in[8];
    const float* gru_Wh        = (const float*)d_in[9];
    const float* gru_b         = (const float*)d_in[10];
    const float* dec_W1        = (const float*)d_in[11];
    const float* dec_b1        = (const float*)d_in[12];
    const float* dec_W2        = (const float*)d_in[13];
    const float* dec_b2        = (const float*)d_in[14];
    const float* dual_W1       = (const float*)d_in[15];
    const float* dual_b1       = (const float*)d_in[16];
    const float* dual_W2       = (const float*)d_in[17];
    const float* dual_b2       = (const float*)d_in[18];
    const int*   adj           = (const int*)d_in[19];
    const int*   inv_adj       = (const int*)d_in[20];
    const int*   in_idx        = (const int*)d_in[21];
    const int*   rev_idx       = (const int*)d_in[22];
    const int*   num_nodes     = (const int*)d_in[23];
    float* out = (float*)d_out;

    cudaFuncSetAttribute(k_gru,  cudaFuncAttributeMaxDynamicSharedMemorySize, GRU_SMEM);
    cudaFuncSetAttribute(k_gat,  cudaFuncAttributeMaxDynamicSharedMemorySize, GAT_SMEM);
    cudaFuncSetAttribute(k_flow, cudaFuncAttributeMaxDynamicSharedMemorySize, FLOW_SMEM);

    k_enc<<<BV/4 + 16, 256>>>(node_features, emb, enc_W, enc_b);

    for (int l=0; l<2; l++){
        k_gat    <<<NCPAD/128, 256, GAT_SMEM>>>(gat_W, gat_b, gat_a);
        k_attnagg<<<BV/8, 256>>>(adj, num_nodes);
        k_gru    <<<NCPAD/128, 256, GRU_SMEM>>>(gru_Wx, gru_Wh, gru_b);
    }

    // flow branch
    k_mlp<<<(NC+127)/128, 128>>>(0, dec_W1, dec_b1, dec_W2, dec_b2);
    k_inattn <<<BV/8, 256>>>(in_idx, inv_adj, adj, num_nodes);
    k_revnorm<<<BV/8, 256>>>(rev_idx, adj, num_nodes);
    k_flow<<<BB, 1024, FLOW_SMEM>>>(demands, inv_adj, in_idx, num_nodes);

    // dual branch
    k_nodestates<<<BV/8, 256>>>(adj, num_nodes);
    k_mlp<<<BV/128, 128>>>(1, dual_W1, dual_b1, dual_W2, dual_b2);
    k_dual<<<BVD/256, 256>>>(adj, num_nodes, demands);

    k_finalize<<<1, 256>>>(out);
}

// round 5
// speedup vs baseline: 19.1403x; 1.0305x over previous
#include <cuda_runtime.h>
#include <math.h>

#define BB 8
#define VV 2048
#define DD 16
#define FF 64
#define EMBD 32
#define HID 32
#define FEAT 16
#define BV (BB*VV)            // 16384
#define BVD (BV*DD)           // 262144
#define VD (VV*DD)            // 32768
#define NC (BV+1)             // 16385 classes (+1 global masked class)
#define NCPAD (65*256)        // 16640
#define BIGC 1e9f

// ---------------- packed f32x2 helpers ----------------------------------------
__device__ __forceinline__ unsigned long long pack2(float lo, float hi){
    unsigned long long r;
    asm("mov.b64 %0, {%1, %2};" : "=l"(r) : "f"(lo), "f"(hi));
    return r;
}
__device__ __forceinline__ void unpack2(unsigned long long v, float& lo, float& hi){
    asm("mov.b64 {%0, %1}, %2;" : "=f"(lo), "=f"(hi) : "l"(v));
}
__device__ __forceinline__ void fma2(unsigned long long& d, unsigned long long a, unsigned long long b){
    asm("fma.rn.f32x2 %0, %1, %2, %0;" : "+l"(d) : "l"(a), "l"(b));
}

// ---------------- scratch (device globals) -----------------------------------
__device__ float g_enc[BV*FF];
__device__ float g_S[NCPAD*FF];      // per-class state
__device__ float g_H[NCPAD*FF];      // per-class tanh(state@W+b)
__device__ float g_sc[NCPAD];        // per-class gat score
__device__ float g_agg[BV*FF];       // per-node agg
__device__ float g_nwc[NCPAD];       // per-class decoder output
__device__ float g_attnin[BVD];
__device__ float g_norm[BVD];
__device__ float g_ns[BV*FF];
__device__ float g_dualvars[BV];
__device__ float g_fc[BB];
__device__ float g_dq[BVD/256];

// ---------------- 1. fused emb-normalize + encoder + S init -------------------
__global__ void k_enc(const float* __restrict__ nf, const float* __restrict__ emb,
                      const float* __restrict__ W, const float* __restrict__ bvec){
    if (blockIdx.x >= BV/4){
        int i = (blockIdx.x - BV/4)*256 + threadIdx.x;     // float4 units, 4096 total
        ((float4*)(g_S + (size_t)BV*FF))[i] = make_float4(0.f,0.f,0.f,0.f);
        return;
    }
    __shared__ float sEmb[4*EMBD];
    int t = threadIdx.x;
    int w = t >> 5, lane = t & 31;
    if (w < 4){
        int v = (blockIdx.x*4 + w) & (VV-1);
        float x = emb[v*EMBD + lane];
        float s = x*x;
        #pragma unroll
        for (int o=16;o;o>>=1) s += __shfl_xor_sync(0xffffffffu, s, o);
        float nrm = sqrtf(s);
        float scale = fminf(1.0f, 1.0f / fmaxf(nrm, 1e-12f));
        sEmb[w*EMBD + lane] = x*scale;
    }
    __syncthreads();
    int nl = t >> 6, f = t & 63;
    int node = blockIdx.x*4 + nl;
    float acc = bvec[f];
    const float* ev = sEmb + nl*EMBD;
    const float* nr = nf + node*FEAT;
    #pragma unroll
    for (int k=0;k<EMBD;k++) acc += ev[k]*W[k*FF+f];
    #pragma unroll
    for (int k=0;k<FEAT;k++) acc += nr[k]*W[(EMBD+k)*FF+f];
    g_enc[node*FF+f] = acc;
    g_S[(size_t)node*FF+f] = acc;
}

// ---------------- 2. per-class GAT: H = tanh(S@W+b), sc = H.a ------------------
// 128 rows/block, 512 threads: 4 threads per row, each 2 f-chunks of 8.
#define GAT_SMEM ((64*64 + 128*64) * (int)sizeof(float))
__global__ void __launch_bounds__(512) k_gat(const float* __restrict__ W,
                                             const float* __restrict__ bvec,
                                             const float* __restrict__ gat_a){
    extern __shared__ float sh[];
    float* Ws   = sh;                 // 64*64
    float* tile = sh + 64*64;         // 128*64 swizzled
    __shared__ float scpart[512];
    int t = threadIdx.x;
    size_t base = (size_t)blockIdx.x * 128;
    for (int i=t;i<64*64;i+=512) Ws[i] = W[i];
    for (int i=t;i<128*64;i+=512){
        int row = i>>6, k = i&63;
        tile[(row<<6) | (k ^ (row&31))] = g_S[base*FF + i];
    }
    __syncthreads();
    int row = t & 127, quarter = t >> 7;
    const float* srow = tile + (row<<6);
    int c = row & 31;
    size_t orow = (base + row) * FF;
    bool live = (base + row) < NC;
    float sc = 0.f;
    #pragma unroll
    for (int fo=0; fo<2; fo++){
        int f = (quarter*2 + fo)*8;
        unsigned long long acc[4];
        {
            float b8[8];
            *(float4*)&b8[0] = __ldg((const float4*)(bvec+f));
            *(float4*)&b8[4] = __ldg((const float4*)(bvec+f+4));
            #pragma unroll
            for (int j=0;j<4;j++) acc[j] = pack2(b8[2*j], b8[2*j+1]);
        }
        #pragma unroll 4
        for (int k=0;k<64;k++){
            float skf = srow[k ^ c];
            unsigned long long sk2 = pack2(skf, skf);
            const ulonglong2* wp = (const ulonglong2*)(Ws + k*64 + f);
            ulonglong2 w01 = wp[0], w23 = wp[1];
            fma2(acc[0], w01.x, sk2);
            fma2(acc[1], w01.y, sk2);
            fma2(acc[2], w23.x, sk2);
            fma2(acc[3], w23.y, sk2);
        }
        float av[8], hv[8];
        *(float4*)&av[0] = __ldg((const float4*)(gat_a+f));
        *(float4*)&av[4] = __ldg((const float4*)(gat_a+f+4));
        #pragma unroll
        for (int j=0;j<4;j++){
            float a0,a1; unpack2(acc[j], a0, a1);
            hv[2*j]   = tanhf(a0);
            hv[2*j+1] = tanhf(a1);
            sc += hv[2*j]*av[2*j] + hv[2*j+1]*av[2*j+1];
        }
        if (live){
            *(float4*)(g_H + orow + f)     = *(float4*)&hv[0];
            *(float4*)(g_H + orow + f + 4) = *(float4*)&hv[4];
        }
    }
    scpart[t] = sc;
    __syncthreads();
    if (t < 128 && (base + t) < NC)
        g_sc[base + t] = (scpart[t] + scpart[t+128]) + (scpart[t+256] + scpart[t+384]);
}

// ---------------- 3. per-node softmax(D) + agg from class rows ------------------
__global__ void k_attnagg(const int* __restrict__ adj, const int* __restrict__ num_nodes){
    int lane = threadIdx.x & 31;
    int node = blockIdx.x*8 + (threadIdx.x >> 5);
    int b = node >> 11;
    int nn = num_nodes[b];
    int c = 0;
    float sc = -1e30f;
    if (lane < DD){
        int a = adj[node*DD+lane];
        bool m = (a==nn);
        c = m ? BV : ((b<<11)+a);
        sc = g_sc[c] - (m ? BIGC : 0.f);
    }
    float mx = sc;
    #pragma unroll
    for (int o=16;o;o>>=1) mx = fmaxf(mx, __shfl_xor_sync(0xffffffffu, mx, o));
    float e = (lane < DD) ? __expf(sc - mx) : 0.f;
    float sm = e;
    #pragma unroll
    for (int o=16;o;o>>=1) sm += __shfl_xor_sync(0xffffffffu, sm, o);
    float attn = e / sm;
    float a0=0.f, a1=0.f;
    #pragma unroll
    for (int d=0;d<DD;d++){
        float ad = __shfl_sync(0xffffffffu, attn, d);
        int  cd = __shfl_sync(0xffffffffu, c, d);
        const float* hr = g_H + (size_t)cd*FF;
        a0 += ad * hr[lane];
        a1 += ad * hr[lane + 32];
    }
    g_agg[node*FF + lane]      = a0;
    g_agg[node*FF + lane + 32] = a1;
}

// ---------------- 4. per-class GRU: S = GRU(agg+enc, S) -------------------------
// 128 rows/block, 512 threads: 4 per row, 2 f-chunks each. f32x2 FMA.
#define GRU_SMEM ((2*64*192 + 2*128*64) * (int)sizeof(float))
__global__ void __launch_bounds__(512, 1) k_gru(const float* __restrict__ Wx,
                                                const float* __restrict__ Wh,
                                                const float* __restrict__ bvec){
    extern __shared__ float sh[];
    float* Wxs = sh;                   // 64*192
    float* Whs = sh + 64*192;
    float* ms  = sh + 2*64*192;        // 128*64 swizzled
    float* ss  = ms + 128*64;
    int t = threadIdx.x;
    size_t base = (size_t)blockIdx.x * 128;
    {
        const float4* wx4 = (const float4*)Wx;
        const float4* wh4 = (const float4*)Wh;
        float4* wxs4 = (float4*)Wxs;
        float4* whs4 = (float4*)Whs;
        for (int i=t;i<64*192/4;i+=512){ wxs4[i]=wx4[i]; whs4[i]=wh4[i]; }
    }
    for (int i=t;i<128*64;i+=512){
        int row = i>>6, k = i&63;
        size_t gr = base + row;
        int sw = (row<<6) | (k ^ (row&31));
        float mv = 0.f;
        if (gr < BV) mv = g_agg[gr*FF+k] + g_enc[gr*FF+k];
        ms[sw] = mv;
        ss[sw] = g_S[gr*FF + k];
    }
    __syncthreads();
    int row = t & 127, quarter = t >> 7;
    if (base + row >= NC) return;
    const float* mrow = ms + (row<<6);
    const float* srow = ss + (row<<6);
    int c = row & 31;
    size_t orow = (base + row) * FF;
    #pragma unroll
    for (int fo=0; fo<2; fo++){
        int f = (quarter*2 + fo)*8;
        unsigned long long X0[4],X1[4],X2[4],H0[4],H1[4],H2[4];
        #pragma unroll
        for (int j=0;j<4;j++){X0[j]=0ull;X1[j]=0ull;X2[j]=0ull;H0[j]=0ull;H1[j]=0ull;H2[j]=0ull;}
        #pragma unroll 2
        for (int k=0;k<64;k++){
            float mkf = mrow[k ^ c];
            float skf = srow[k ^ c];
            unsigned long long mk2 = pack2(mkf, mkf);
            unsigned long long sk2 = pack2(skf, skf);
            const float* wxp = Wxs + k*192 + f;
            const float* whp = Whs + k*192 + f;
            ulonglong2 xa = ((const ulonglong2*)(wxp))[0];
            ulonglong2 xa2= ((const ulonglong2*)(wxp+4))[0];
            ulonglong2 xb = ((const ulonglong2*)(wxp+64))[0];
            ulonglong2 xb2= ((const ulonglong2*)(wxp+68))[0];
            ulonglong2 xc = ((const ulonglong2*)(wxp+128))[0];
            ulonglong2 xc2= ((const ulonglong2*)(wxp+132))[0];
            ulonglong2 ha = ((const ulonglong2*)(whp))[0];
            ulonglong2 ha2= ((const ulonglong2*)(whp+4))[0];
            ulonglong2 hb = ((const ulonglong2*)(whp+64))[0];
            ulonglong2 hb2= ((const ulonglong2*)(whp+68))[0];
            ulonglong2 hc = ((const ulonglong2*)(whp+128))[0];
            ulonglong2 hc2= ((const ulonglong2*)(whp+132))[0];
            fma2(X0[0], xa.x, mk2);  fma2(X0[1], xa.y, mk2);
            fma2(X0[2], xa2.x, mk2); fma2(X0[3], xa2.y, mk2);
            fma2(X1[0], xb.x, mk2);  fma2(X1[1], xb.y, mk2);
            fma2(X1[2], xb2.x, mk2); fma2(X1[3], xb2.y, mk2);
            fma2(X2[0], xc.x, mk2);  fma2(X2[1], xc.y, mk2);
            fma2(X2[2], xc2.x, mk2); fma2(X2[3], xc2.y, mk2);
            fma2(H0[0], ha.x, sk2);  fma2(H0[1], ha.y, sk2);
            fma2(H0[2], ha2.x, sk2); fma2(H0[3], ha2.y, sk2);
            fma2(H1[0], hb.x, sk2);  fma2(H1[1], hb.y, sk2);
            fma2(H1[2], hb2.x, sk2); fma2(H1[3], hb2.y, sk2);
            fma2(H2[0], hc.x, sk2);  fma2(H2[1], hc.y, sk2);
            fma2(H2[2], hc2.x, sk2); fma2(H2[3], hc2.y, sk2);
        }
        float bz[8], br8[8], bh[8], o[8];
        *(float4*)&bz[0]  = __ldg((const float4*)(bvec+f));
        *(float4*)&bz[4]  = __ldg((const float4*)(bvec+f+4));
        *(float4*)&br8[0] = __ldg((const float4*)(bvec+64+f));
        *(float4*)&br8[4] = __ldg((const float4*)(bvec+64+f+4));
        *(float4*)&bh[0]  = __ldg((const float4*)(bvec+128+f));
        *(float4*)&bh[4]  = __ldg((const float4*)(bvec+128+f+4));
        #pragma unroll
        for (int j=0;j<4;j++){
            float x0a,x0b,x1a,x1b,x2a,x2b,h0a,h0b,h1a,h1b,h2a,h2b;
            unpack2(X0[j],x0a,x0b); unpack2(X1[j],x1a,x1b); unpack2(X2[j],x2a,x2b);
            unpack2(H0[j],h0a,h0b); unpack2(H1[j],h1a,h1b); unpack2(H2[j],h2a,h2b);
            {
                float z    = 1.f/(1.f + __expf(-(x0a + bz[2*j]  + h0a)));
                float r    = 1.f/(1.f + __expf(-(x1a + br8[2*j] + h1a)));
                float cand = tanhf(x2a + bh[2*j] + r*h2a);
                float sold = srow[(f+2*j) ^ c];
                o[2*j] = z*sold + (1.f - z)*cand;
            }
            {
                float z    = 1.f/(1.f + __expf(-(x0b + bz[2*j+1]  + h0b)));
                float r    = 1.f/(1.f + __expf(-(x1b + br8[2*j+1] + h1b)));
                float cand = tanhf(x2b + bh[2*j+1] + r*h2b);
                float sold = srow[(f+2*j+1) ^ c];
                o[2*j+1] = z*sold + (1.f - z)*cand;
            }
        }
        *(float4*)(g_S + orow + f)     = *(float4*)&o[0];
        *(float4*)(g_S + orow + f + 4) = *(float4*)&o[4];
    }
}

// ---------------- 5. 64->32->1 MLP head -------------------------------------------
__global__ void k_mlp(int mode, const float* __restrict__ W1, const float* __restrict__ b1,
                      const float* __restrict__ W2, const float* __restrict__ b2){
    __shared__ float S[128*65];
    __shared__ float W1s[64*32];
    __shared__ float b1s[32], W2s[32];
    const float* in = mode ? g_ns : g_S;
    float* out      = mode ? g_dualvars : g_nwc;
    int nrows       = mode ? BV : NC;
    int t = threadIdx.x;
    int base = blockIdx.x*128;
    for (int i=t;i<2048;i+=128) W1s[i] = W1[i];
    if (t < 32){ b1s[t] = b1[t]; W2s[t] = W2[t]; }
    for (int c=0;c<64;c++){
        int lin = c*128 + t;
        int r = lin >> 6, k = lin & 63;
        S[r*65 + k] = in[(size_t)base*FF + lin];
    }
    __syncthreads();
    if (base + t >= nrows) return;
    float acc[32];
    #pragma unroll
    for (int h=0;h<32;h++) acc[h] = b1s[h];
    const float* myrow = S + t*65;
    for (int k=0;k<64;k++){
        float s = myrow[k];
        #pragma unroll
        for (int h=0;h<32;h++) acc[h] += s*W1s[k*32+h];
    }
    float o = b2[0];
    #pragma unroll
    for (int h=0;h<32;h++) o += tanhf(acc[h])*W2s[h];
    out[base + t] = o;
}

// ---------------- 6. incoming-gather softmax (expand fused) -----------------------
__global__ void k_inattn(const int* __restrict__ in_idx, const int* __restrict__ inv_adj,
                         const int* __restrict__ adj, const int* __restrict__ num_nodes){
    int lane = threadIdx.x & 31;
    int node = blockIdx.x*8 + (threadIdx.x >> 5);
    int b = node >> 11;
    int nn = num_nodes[b];
    float sc = -1e30f;
    if (lane < DD){
        int idx = in_idx[node*DD + lane];
        int a2 = adj[b*VD + idx];
        float inc = g_nwc[(a2==nn) ? BV : ((b<<11)+a2)];
        int ia = inv_adj[node*DD + lane];
        sc = inc - ((ia == nn) ? BIGC : 0.f);
    }
    float mx = sc;
    #pragma unroll
    for (int o=16;o;o>>=1) mx = fmaxf(mx, __shfl_xor_sync(0xffffffffu, mx, o));
    float e = (lane < DD) ? __expf(sc - mx) : 0.f;
    float sm = e;
    #pragma unroll
    for (int o=16;o;o>>=1) sm += __shfl_xor_sync(0xffffffffu, sm, o);
    if (lane < DD) g_attnin[node*DD + lane] = e / sm;
}

// ---------------- 7. rev-gather + masked softmax -> normalized ---------------------
__global__ void k_revnorm(const int* __restrict__ rev_idx, const int* __restrict__ adj,
                          const int* __restrict__ num_nodes){
    int lane = threadIdx.x & 31;
    int node = blockIdx.x*8 + (threadIdx.x >> 5);
    int b = node >> 11;
    float sc = -1e30f;
    if (lane < DD){
        int ridx = rev_idx[node*DD + lane];
        float val = g_attnin[b*VD + ridx];
        int a = adj[node*DD + lane];
        sc = val - ((a == num_nodes[b]) ? BIGC : 0.f);
    }
    float mx = sc;
    #pragma unroll
    for (int o=16;o;o>>=1) mx = fmaxf(mx, __shfl_xor_sync(0xffffffffu, mx, o));
    float e = (lane < DD) ? __expf(sc - mx) : 0.f;
    float sm = e;
    #pragma unroll
    for (int o=16;o;o>>=1) sm += __shfl_xor_sync(0xffffffffu, sm, o);
    if (lane < DD) g_norm[node*DD + lane] = e / sm;
}

// ---------------- 8. flow fixed-point on node vector t, 1 block/batch ---------------
#define FLOW_SMEM ((VD + VV + VV + 1024) * (int)sizeof(float))
__global__ void __launch_bounds__(1024) k_flow(const float* __restrict__ demands,
                                               const int* __restrict__ inv_adj,
                                               const int* __restrict__ in_idx,
                                               const int* __restrict__ num_nodes){
    extern __shared__ float sh[];
    float* wT  = sh;              // [DD][VV] transposed weights
    float* ts  = sh + VD;         // VV
    float* sup = ts + VV;         // VV
    float* red = sup + VV;        // 1024
    int b = blockIdx.x, t = threadIdx.x;
    int nn = num_nodes[b];
    unsigned int sp[2][8];        // packed source node indices (16-bit)
    float nsq[2];
    #pragma unroll
    for (int n=0;n<2;n++){
        int v = t + n*1024;
        size_t ebase = ((size_t)b*VV + v)*DD;
        int ia[DD], m[DD];
        #pragma unroll
        for (int d=0;d<DD;d+=4){
            *(int4*)&ia[d] = __ldg((const int4*)(inv_adj + ebase + d));
            *(int4*)&m[d]  = __ldg((const int4*)(in_idx  + ebase + d));
        }
        float nrm[DD];
        #pragma unroll
        for (int d=0;d<DD;d+=4)
            *(float4*)&nrm[d] = __ldg((const float4*)(g_norm + (size_t)b*VD + v*DD + d));
        float q = 0.f;
        #pragma unroll
        for (int d=0;d<DD;d++) q += nrm[d]*nrm[d];
        nsq[n] = q;
        #pragma unroll
        for (int d=0;d<DD;d++){
            float wv = (ia[d]==nn) ? 0.f : g_norm[(size_t)b*VD + m[d]];
            wT[d*VV + v] = wv;
            int sv = m[d] >> 4;
            if ((d&1)==0) sp[n][d>>1] = (unsigned int)sv;
            else          sp[n][d>>1] |= ((unsigned int)sv) << 16;
        }
        float s = fmaxf(-demands[b*VV + v], 0.f);
        sup[v] = s;
        ts[v] = s;
    }
    __syncthreads();
    for (int it=0; it<10; it++){
        float acc[2] = {0.f, 0.f};
        #pragma unroll
        for (int n=0;n<2;n++){
            int v = t + n*1024;
            #pragma unroll
            for (int d=0;d<DD;d++){
                unsigned int pk = sp[n][d>>1];
                int sv = (d&1) ? (pk>>16) : (pk & 0xffff);
                acc[n] += wT[d*VV + v] * ts[sv];
            }
        }
        __syncthreads();
        ts[t]        = sup[t]        + acc[0];
        ts[t + 1024] = sup[t + 1024] + acc[1];
        __syncthreads();
    }
    float c = nsq[0]*ts[t]*ts[t] + nsq[1]*ts[t+1024]*ts[t+1024];
    red[t] = c; __syncthreads();
    for (int s=512; s>0; s>>=1){ if (t < s) red[t] += red[t+s]; __syncthreads(); }
    if (t == 0) g_fc[b] = red[0];
}

// ---------------- 9. node_states = sum over d of class rows -------------------------
__global__ void k_nodestates(const int* __restrict__ adj, const int* __restrict__ num_nodes){
    int lane = threadIdx.x & 31;
    int node = blockIdx.x*8 + (threadIdx.x >> 5);
    int b = node >> 11;
    int nn = num_nodes[b];
    int c = 0;
    if (lane < DD){
        int a = adj[node*DD+lane];
        c = (a==nn) ? BV : ((b<<11)+a);
    }
    float s0=0.f, s1=0.f;
    #pragma unroll
    for (int d=0;d<DD;d++){
        int cd = __shfl_sync(0xffffffffu, c, d);
        const float* sr = g_S + (size_t)cd*FF;
        s0 += sr[lane];
        s1 += sr[lane + 32];
    }
    g_ns[node*FF + lane]      = s0;
    g_ns[node*FF + lane + 32] = s1;
}

// ---------------- 10. dual iterations + quad cost + demand fold ----------------------
__global__ void k_dual(const int* __restrict__ adj, const int* __restrict__ num_nodes,
                       const float* __restrict__ demands){
    __shared__ float red[256];
    int idx = blockIdx.x*256 + threadIdx.x;
    int b = idx >> 15; int node = idx >> 4;
    int a = adj[idx]; int nn = num_nodes[b];
    float mask = (a==nn) ? 1.f : 0.f;
    float valid = 1.f - mask;
    float dv  = g_dualvars[node];
    float dtr = g_dualvars[(b<<11) + a] * valid;
    float dd  = dtr - mask*dv;
    float f = 0.f, ac = 0.f;
    #pragma unroll
    for (int i=0;i<10;i++){
        float g = 2.f*f + dd;
        ac = 0.9f*ac + 0.01f*g;
        f = fmaxf(f - ac, 0.f) * valid;
    }
    float c = f*f + dd*f;
    if ((idx & 15) == 0) c -= dv * demands[node];     // fold dual_demand (once per node)
    red[threadIdx.x] = c; __syncthreads();
    for (int s=128; s>0; s>>=1){ if (threadIdx.x < s) red[threadIdx.x] += red[threadIdx.x+s]; __syncthreads(); }
    if (threadIdx.x == 0) g_dq[blockIdx.x] = red[0];
}

// ---------------- 11. finalize: out[b] = fc - sum(dq partials) ------------------------
__global__ void k_finalize(float* __restrict__ out){
    int w = threadIdx.x >> 5, lane = threadIdx.x & 31;
    if (w < BB){
        float dq = 0.f;
        #pragma unroll
        for (int i=0;i<4;i++) dq += g_dq[w*128 + lane + 32*i];
        #pragma unroll
        for (int o=16;o;o>>=1) dq += __shfl_xor_sync(0xffffffffu, dq, o);
        if (lane == 0) out[w] = g_fc[w] - dq;
    }
}

// ---------------- launcher -------------------------------------------------------------
extern "C" void kernel_launch(void* const* d_in, const int* in_sizes, int n_in,
                              void* d_out, int out_size){
    const float* node_features = (const float*)d_in[0];
    const float* demands       = (const float*)d_in[1];
    const float* emb           = (const float*)d_in[2];
    const float* enc_W         = (const float*)d_in[3];
    const float* enc_b         = (const float*)d_in[4];
    const float* gat_W         = (const float*)d_in[5];
    const float* gat_b         = (const float*)d_in[6];
    const float* gat_a         = (const float*)d_in[7];
    const float* gru_Wx        = (const float*)d_in[8];
    const float* gru_Wh        = (const float*)d_in[9];
    const float* gru_b         = (const float*)d_in[10];
    const float* dec_W1        = (const float*)d_in[11];
    const float* dec_b1        = (const float*)d_in[12];
    const float* dec_W2        = (const float*)d_in[13];
    const float* dec_b2        = (const float*)d_in[14];
    const float* dual_W1       = (const float*)d_in[15];
    const float* dual_b1       = (const float*)d_in[16];
    const float* dual_W2       = (const float*)d_in[17];
    const float* dual_b2       = (const float*)d_in[18];
    const int*   adj           = (const int*)d_in[19];
    const int*   inv_adj       = (const int*)d_in[20];
    const int*   in_idx        = (const int*)d_in[21];
    const int*   rev_idx       = (const int*)d_in[22];
    const int*   num_nodes     = (const int*)d_in[23];
    float* out = (float*)d_out;

    cudaFuncSetAttribute(k_gru,  cudaFuncAttributeMaxDynamicSharedMemorySize, GRU_SMEM);
    cudaFuncSetAttribute(k_gat,  cudaFuncAttributeMaxDynamicSharedMemorySize, GAT_SMEM);
    cudaFuncSetAttribute(k_flow, cudaFuncAttributeMaxDynamicSharedMemorySize, FLOW_SMEM);

    k_enc<<<BV/4 + 16, 256>>>(node_features, emb, enc_W, enc_b);

    for (int l=0; l<2; l++){
        k_gat    <<<NCPAD/128, 512, GAT_SMEM>>>(gat_W, gat_b, gat_a);
        k_attnagg<<<BV/8, 256>>>(adj, num_nodes);
        k_gru    <<<NCPAD/128, 512, GRU_SMEM>>>(gru_Wx, gru_Wh, gru_b);
    }

    // flow branch
    k_mlp<<<(NC+127)/128, 128>>>(0, dec_W1, dec_b1, dec_W2, dec_b2);
    k_inattn <<<BV/8, 256>>>(in_idx, inv_adj, adj, num_nodes);
    k_revnorm<<<BV/8, 256>>>(rev_idx, adj, num_nodes);
    k_flow<<<BB, 1024, FLOW_SMEM>>>(demands, inv_adj, in_idx, num_nodes);

    // dual branch
    k_nodestates<<<BV/8, 256>>>(adj, num_nodes);
    k_mlp<<<BV/128, 128>>>(1, dual_W1, dual_b1, dual_W2, dual_b2);
    k_dual<<<BVD/256, 256>>>(adj, num_nodes, demands);

    k_finalize<<<1, 256>>>(out);
}